// round 1
// baseline (speedup 1.0000x reference)
#include <cuda_runtime.h>

typedef unsigned long long u64;

__device__ __forceinline__ u64 pk2(float lo, float hi) {
    u64 r; asm("mov.b64 %0, {%1, %2};" : "=l"(r) : "f"(lo), "f"(hi)); return r;
}
__device__ __forceinline__ void upk2(u64 v, float& lo, float& hi) {
    asm("mov.b64 {%0, %1}, %2;" : "=f"(lo), "=f"(hi) : "l"(v));
}
__device__ __forceinline__ u64 ffma2(u64 a, u64 b, u64 c) {
    u64 d; asm("fma.rn.f32x2 %0, %1, %2, %3;" : "=l"(d) : "l"(a), "l"(b), "l"(c)); return d;
}

constexpr int SZ_WS0 = 3 * 64;
constexpr int SZ_WS1 = 64 * 64;
constexpr int SZ_WS2 = 64 * 16;
constexpr int SZ_WC0 = 18 * 64;
constexpr int SZ_WC1 = 64 * 64;
constexpr int SZ_WC2 = 64 * 64;
constexpr int SZ_WC3 = 64 * 3;
constexpr int SMEM_FLOATS = SZ_WS0 + SZ_WS1 + SZ_WS2 + SZ_WC0 + SZ_WC1 + SZ_WC2 + SZ_WC3; // 14848
constexpr int TPB = 256;
constexpr int PPT = 4;

// hin[K] in registers, weights in smem row-major [K][NOUT].
// Accumulates NOUT/2 packed f32x2 output pairs.
template<int K, int NOUT>
__device__ __forceinline__ void layer_pairs(const float* hin, const float* Ws, u64* acc) {
    constexpr int NP = NOUT / 2;
    #pragma unroll
    for (int j = 0; j < NP; j++) acc[j] = 0ull;
    #pragma unroll
    for (int k = 0; k < K; k++) {
        u64 a = pk2(hin[k], hin[k]);
        const ulonglong2* wr = reinterpret_cast<const ulonglong2*>(Ws + k * NOUT);
        #pragma unroll
        for (int q = 0; q < NP / 2; q++) {
            ulonglong2 w = wr[q];               // LDS.128: 4 weights = 2 f32x2 pairs
            acc[2 * q]     = ffma2(a, w.x, acc[2 * q]);
            acc[2 * q + 1] = ffma2(a, w.y, acc[2 * q + 1]);
        }
    }
}

template<int NOUT>
__device__ __forceinline__ void unpack_relu(const u64* acc, float* hout) {
    #pragma unroll
    for (int j = 0; j < NOUT / 2; j++) {
        float lo, hi; upk2(acc[j], lo, hi);
        hout[2 * j]     = fmaxf(lo, 0.0f);
        hout[2 * j + 1] = fmaxf(hi, 0.0f);
    }
}

__global__ void __launch_bounds__(TPB) nerf_small_kernel(
    const float* __restrict__ x,
    const float* __restrict__ ws0, const float* __restrict__ ws1,
    const float* __restrict__ ws2, const float* __restrict__ wc0,
    const float* __restrict__ wc1, const float* __restrict__ wc2,
    const float* __restrict__ wc3,
    float* __restrict__ out, int n)
{
    extern __shared__ float sw[];
    float* S0 = sw;
    float* S1 = S0 + SZ_WS0;
    float* S2 = S1 + SZ_WS1;
    float* C0 = S2 + SZ_WS2;
    float* C1 = C0 + SZ_WC0;
    float* C2 = C1 + SZ_WC1;
    float* C3 = C2 + SZ_WC2;

    for (int t = threadIdx.x; t < SZ_WS0; t += TPB) S0[t] = ws0[t];
    for (int t = threadIdx.x; t < SZ_WS1; t += TPB) S1[t] = ws1[t];
    for (int t = threadIdx.x; t < SZ_WS2; t += TPB) S2[t] = ws2[t];
    for (int t = threadIdx.x; t < SZ_WC0; t += TPB) C0[t] = wc0[t];
    for (int t = threadIdx.x; t < SZ_WC1; t += TPB) C1[t] = wc1[t];
    for (int t = threadIdx.x; t < SZ_WC2; t += TPB) C2[t] = wc2[t];
    for (int t = threadIdx.x; t < SZ_WC3; t += TPB) C3[t] = wc3[t];
    __syncthreads();

    int base = blockIdx.x * (TPB * PPT);
    #pragma unroll 1
    for (int p = 0; p < PPT; p++) {
        int i = base + p * TPB + threadIdx.x;
        if (i >= n) continue;

        const float* xi = x + (size_t)i * 6;
        float in0[3] = { xi[0], xi[1], xi[2] };
        float vw[3]  = { xi[3], xi[4], xi[5] };

        u64 acc[32];
        float h[64];

        // sigma branch: 3 -> 64 -> 64 -> 16
        layer_pairs<3, 64>(in0, S0, acc);
        unpack_relu<64>(acc, h);
        layer_pairs<64, 64>(h, S1, acc);
        unpack_relu<64>(acc, h);
        layer_pairs<64, 16>(h, S2, acc);
        float g[16];
        #pragma unroll
        for (int j = 0; j < 8; j++) { upk2(acc[j], g[2 * j], g[2 * j + 1]); }

        // stable softplus (matches jax.nn.softplus)
        float s = g[0];
        float sigma = fmaxf(s, 0.0f) + log1pf(expf(-fabsf(s)));

        // color branch: concat(views, geo_feat) = 18 -> 64 -> 64 -> 64 -> 3
        float cin[18];
        cin[0] = vw[0]; cin[1] = vw[1]; cin[2] = vw[2];
        #pragma unroll
        for (int j = 0; j < 15; j++) cin[3 + j] = g[1 + j];

        layer_pairs<18, 64>(cin, C0, acc);
        unpack_relu<64>(acc, h);
        layer_pairs<64, 64>(h, C1, acc);
        unpack_relu<64>(acc, h);
        layer_pairs<64, 64>(h, C2, acc);
        unpack_relu<64>(acc, h);

        float c0 = 0.f, c1 = 0.f, c2 = 0.f;
        #pragma unroll
        for (int k = 0; k < 64; k++) {
            float hk = h[k];
            c0 = fmaf(hk, C3[k * 3 + 0], c0);
            c1 = fmaf(hk, C3[k * 3 + 1], c1);
            c2 = fmaf(hk, C3[k * 3 + 2], c2);
        }

        float4 o; o.x = c0; o.y = c1; o.z = c2; o.w = sigma;
        reinterpret_cast<float4*>(out)[i] = o;
    }
}

extern "C" void kernel_launch(void* const* d_in, const int* in_sizes, int n_in,
                              void* d_out, int out_size) {
    const float* x   = (const float*)d_in[0];
    const float* ws0 = (const float*)d_in[1];
    const float* ws1 = (const float*)d_in[2];
    const float* ws2 = (const float*)d_in[3];
    const float* wc0 = (const float*)d_in[4];
    const float* wc1 = (const float*)d_in[5];
    const float* wc2 = (const float*)d_in[6];
    const float* wc3 = (const float*)d_in[7];
    float* out = (float*)d_out;

    int n = in_sizes[0] / 6;
    size_t smem = SMEM_FLOATS * sizeof(float);  // 59392 B -> needs opt-in
    cudaFuncSetAttribute(nerf_small_kernel,
                         cudaFuncAttributeMaxDynamicSharedMemorySize, (int)smem);
    int blocks = (n + TPB * PPT - 1) / (TPB * PPT);
    nerf_small_kernel<<<blocks, TPB, smem>>>(x, ws0, ws1, ws2, wc0, wc1, wc2, wc3, out, n);
}

// round 2
// speedup vs baseline: 1.0608x; 1.0608x over previous
#include <cuda_runtime.h>

typedef unsigned long long u64;

__device__ __forceinline__ u64 dup2(float v) {
    u64 r; asm("mov.b64 %0, {%1, %1};" : "=l"(r) : "f"(v)); return r;
}
__device__ __forceinline__ void upk2(u64 v, float& lo, float& hi) {
    asm("mov.b64 {%0, %1}, %2;" : "=f"(lo), "=f"(hi) : "l"(v));
}
__device__ __forceinline__ u64 ffma2(u64 a, u64 b, u64 c) {
    u64 d; asm("fma.rn.f32x2 %0, %1, %2, %3;" : "=l"(d) : "l"(a), "l"(b), "l"(c)); return d;
}

constexpr int SZ_WS0 = 3 * 64;
constexpr int SZ_WS1 = 64 * 64;
constexpr int SZ_WS2 = 64 * 16;
constexpr int SZ_WC0 = 18 * 64;
constexpr int SZ_WC1 = 64 * 64;
constexpr int SZ_WC2 = 64 * 64;
constexpr int SZ_WC3 = 64 * 3;
constexpr int SMEM_W = SZ_WS0 + SZ_WS1 + SZ_WS2 + SZ_WC0 + SZ_WC1 + SZ_WC2 + SZ_WC3; // 14848
constexpr int TPB = 256;
constexpr int IPT = 2;                       // pair-iterations per thread
constexpr int BUF_FLOATS = 64 * TPB;         // one activation buffer (pt1)
constexpr size_t SMEM_BYTES = (SMEM_W + 2 * BUF_FLOATS) * sizeof(float); // 190464

// Both points' inputs in registers (small K). acc: NOUT/2 packed pairs per point.
template<int KN, int NOUT>
__device__ __forceinline__ void layer_reg(const float* a0f, const float* a1f,
                                          const float* __restrict__ Ws,
                                          u64* acc0, u64* acc1)
{
    #pragma unroll
    for (int j = 0; j < NOUT / 2; j++) { acc0[j] = 0ull; acc1[j] = 0ull; }
    #pragma unroll
    for (int k = 0; k < KN; k++) {
        u64 a0 = dup2(a0f[k]);
        u64 a1 = dup2(a1f[k]);
        const ulonglong2* wr = reinterpret_cast<const ulonglong2*>(Ws + k * NOUT);
        #pragma unroll
        for (int q = 0; q < NOUT / 4; q++) {
            ulonglong2 w = wr[q];
            acc0[2*q]   = ffma2(a0, w.x, acc0[2*q]);
            acc0[2*q+1] = ffma2(a0, w.y, acc0[2*q+1]);
            acc1[2*q]   = ffma2(a1, w.x, acc1[2*q]);
            acc1[2*q+1] = ffma2(a1, w.y, acc1[2*q+1]);
        }
    }
}

// K=64; pt0 input in regs, pt1 input in smem buffer [k*TPB+tid]. TN-output slice.
template<int TN>
__device__ __forceinline__ void slice_smem(const float* h0,
                                           const float* __restrict__ bin, int tid,
                                           const float* __restrict__ Ws, int ldw, int col0,
                                           u64* acc0, u64* acc1)
{
    #pragma unroll
    for (int j = 0; j < TN / 2; j++) { acc0[j] = 0ull; acc1[j] = 0ull; }
    #pragma unroll
    for (int k = 0; k < 64; k++) {
        u64 a0 = dup2(h0[k]);
        u64 a1 = dup2(bin[k * TPB + tid]);
        const ulonglong2* wr = reinterpret_cast<const ulonglong2*>(Ws + k * ldw + col0);
        #pragma unroll
        for (int q = 0; q < TN / 4; q++) {
            ulonglong2 w = wr[q];
            acc0[2*q]   = ffma2(a0, w.x, acc0[2*q]);
            acc0[2*q+1] = ffma2(a0, w.y, acc0[2*q+1]);
            acc1[2*q]   = ffma2(a1, w.x, acc1[2*q]);
            acc1[2*q+1] = ffma2(a1, w.y, acc1[2*q+1]);
        }
    }
}

// 64->64 layer with relu; pt1 activations ping-pong bin -> bout in smem.
__device__ __forceinline__ void layer64(float* h0, const float* __restrict__ bin,
                                        float* __restrict__ bout, int tid,
                                        const float* __restrict__ Ws)
{
    float nh[64];
    #pragma unroll
    for (int half = 0; half < 2; half++) {
        u64 acc0[16], acc1[16];
        slice_smem<32>(h0, bin, tid, Ws, 64, half * 32, acc0, acc1);
        #pragma unroll
        for (int j = 0; j < 16; j++) {
            float l0, m0; upk2(acc0[j], l0, m0);
            nh[half*32 + 2*j]     = fmaxf(l0, 0.0f);
            nh[half*32 + 2*j + 1] = fmaxf(m0, 0.0f);
            float l1, m1; upk2(acc1[j], l1, m1);
            bout[(half*32 + 2*j)     * TPB + tid] = fmaxf(l1, 0.0f);
            bout[(half*32 + 2*j + 1) * TPB + tid] = fmaxf(m1, 0.0f);
        }
    }
    #pragma unroll
    for (int k = 0; k < 64; k++) h0[k] = nh[k];
}

__global__ void __launch_bounds__(TPB, 1) nerf_small_kernel(
    const float* __restrict__ x,
    const float* __restrict__ ws0, const float* __restrict__ ws1,
    const float* __restrict__ ws2, const float* __restrict__ wc0,
    const float* __restrict__ wc1, const float* __restrict__ wc2,
    const float* __restrict__ wc3,
    float* __restrict__ out, int n)
{
    extern __shared__ float sw[];
    float* S0 = sw;
    float* S1 = S0 + SZ_WS0;
    float* S2 = S1 + SZ_WS1;
    float* C0 = S2 + SZ_WS2;
    float* C1 = C0 + SZ_WC0;
    float* C2 = C1 + SZ_WC1;
    float* C3 = C2 + SZ_WC2;
    float* B0 = sw + SMEM_W;
    float* B1 = B0 + BUF_FLOATS;

    for (int t = threadIdx.x; t < SMEM_W; t += TPB) {
        // weights are laid out back-to-back in the same order as d_in
        float v;
        if      (t < SZ_WS0)                                    v = ws0[t];
        else if (t < SZ_WS0+SZ_WS1)                             v = ws1[t-SZ_WS0];
        else if (t < SZ_WS0+SZ_WS1+SZ_WS2)                      v = ws2[t-SZ_WS0-SZ_WS1];
        else if (t < SZ_WS0+SZ_WS1+SZ_WS2+SZ_WC0)               v = wc0[t-SZ_WS0-SZ_WS1-SZ_WS2];
        else if (t < SZ_WS0+SZ_WS1+SZ_WS2+SZ_WC0+SZ_WC1)        v = wc1[t-SZ_WS0-SZ_WS1-SZ_WS2-SZ_WC0];
        else if (t < SZ_WS0+SZ_WS1+SZ_WS2+SZ_WC0+SZ_WC1+SZ_WC2) v = wc2[t-SZ_WS0-SZ_WS1-SZ_WS2-SZ_WC0-SZ_WC1];
        else                                                    v = wc3[t-SZ_WS0-SZ_WS1-SZ_WS2-SZ_WC0-SZ_WC1-SZ_WC2];
        sw[t] = v;
    }
    __syncthreads();

    const int tid = threadIdx.x;
    const int halfn = n >> 1;
    const int base = blockIdx.x * (TPB * IPT);

    #pragma unroll 1
    for (int it = 0; it < IPT; it++) {
        int P = base + it * TPB + tid;
        if (P >= halfn) continue;
        int i0 = P, i1 = P + halfn;

        const float* x0 = x + (size_t)i0 * 6;
        const float* x1 = x + (size_t)i1 * 6;
        float p0[3] = { x0[0], x0[1], x0[2] };
        float v0[3] = { x0[3], x0[4], x0[5] };
        float p1[3] = { x1[0], x1[1], x1[2] };
        float v1[3] = { x1[3], x1[4], x1[5] };

        u64 acc0[32], acc1[32];
        float h0[64];

        // ---- S0: 3 -> 64, relu; pt1 -> B0 ----
        layer_reg<3, 64>(p0, p1, S0, acc0, acc1);
        #pragma unroll
        for (int j = 0; j < 32; j++) {
            float l0, m0; upk2(acc0[j], l0, m0);
            h0[2*j]   = fmaxf(l0, 0.0f);
            h0[2*j+1] = fmaxf(m0, 0.0f);
            float l1, m1; upk2(acc1[j], l1, m1);
            B0[(2*j)   * TPB + tid] = fmaxf(l1, 0.0f);
            B0[(2*j+1) * TPB + tid] = fmaxf(m1, 0.0f);
        }

        // ---- S1: 64 -> 64, relu; B0 -> B1 ----
        layer64(h0, B0, B1, tid, S1);

        // ---- S2: 64 -> 16 (no relu); pt1 read from B1 ----
        u64 ga0[8], ga1[8];
        slice_smem<16>(h0, B1, tid, S2, 16, 0, ga0, ga1);
        float g0[16], g1[16];
        #pragma unroll
        for (int j = 0; j < 8; j++) {
            upk2(ga0[j], g0[2*j], g0[2*j+1]);
            upk2(ga1[j], g1[2*j], g1[2*j+1]);
        }

        // softplus (stable, matches jax.nn.softplus)
        float s0 = g0[0], s1 = g1[0];
        float sig0 = fmaxf(s0, 0.0f) + log1pf(expf(-fabsf(s0)));
        float sig1 = fmaxf(s1, 0.0f) + log1pf(expf(-fabsf(s1)));

        // ---- color branch input: [views, geo_feat] (18) ----
        float c0in[18], c1in[18];
        c0in[0]=v0[0]; c0in[1]=v0[1]; c0in[2]=v0[2];
        c1in[0]=v1[0]; c1in[1]=v1[1]; c1in[2]=v1[2];
        #pragma unroll
        for (int j = 0; j < 15; j++) { c0in[3+j] = g0[1+j]; c1in[3+j] = g1[1+j]; }

        // ---- C0: 18 -> 64, relu; pt1 -> B0 ----
        layer_reg<18, 64>(c0in, c1in, C0, acc0, acc1);
        #pragma unroll
        for (int j = 0; j < 32; j++) {
            float l0, m0; upk2(acc0[j], l0, m0);
            h0[2*j]   = fmaxf(l0, 0.0f);
            h0[2*j+1] = fmaxf(m0, 0.0f);
            float l1, m1; upk2(acc1[j], l1, m1);
            B0[(2*j)   * TPB + tid] = fmaxf(l1, 0.0f);
            B0[(2*j+1) * TPB + tid] = fmaxf(m1, 0.0f);
        }

        // ---- C1: 64 -> 64, relu; B0 -> B1 ----
        layer64(h0, B0, B1, tid, C1);
        // ---- C2: 64 -> 64, relu; B1 -> B0 ----
        layer64(h0, B1, B0, tid, C2);

        // ---- C3: 64 -> 3 (scalar) ----
        float o00=0.f, o01=0.f, o02=0.f, o10=0.f, o11=0.f, o12=0.f;
        #pragma unroll
        for (int k = 0; k < 64; k++) {
            float a0 = h0[k];
            float a1 = B0[k * TPB + tid];
            float w0 = C3[k*3+0], w1 = C3[k*3+1], w2 = C3[k*3+2];
            o00 = fmaf(a0, w0, o00); o01 = fmaf(a0, w1, o01); o02 = fmaf(a0, w2, o02);
            o10 = fmaf(a1, w0, o10); o11 = fmaf(a1, w1, o11); o12 = fmaf(a1, w2, o12);
        }

        float4 r0; r0.x = o00; r0.y = o01; r0.z = o02; r0.w = sig0;
        float4 r1; r1.x = o10; r1.y = o11; r1.z = o12; r1.w = sig1;
        reinterpret_cast<float4*>(out)[i0] = r0;
        reinterpret_cast<float4*>(out)[i1] = r1;
    }
}

extern "C" void kernel_launch(void* const* d_in, const int* in_sizes, int n_in,
                              void* d_out, int out_size) {
    const float* x   = (const float*)d_in[0];
    const float* ws0 = (const float*)d_in[1];
    const float* ws1 = (const float*)d_in[2];
    const float* ws2 = (const float*)d_in[3];
    const float* wc0 = (const float*)d_in[4];
    const float* wc1 = (const float*)d_in[5];
    const float* wc2 = (const float*)d_in[6];
    const float* wc3 = (const float*)d_in[7];
    float* out = (float*)d_out;

    int n = in_sizes[0] / 6;
    int halfn = n >> 1;

    cudaFuncSetAttribute(nerf_small_kernel,
                         cudaFuncAttributeMaxDynamicSharedMemorySize, (int)SMEM_BYTES);
    int blocks = (halfn + TPB * IPT - 1) / (TPB * IPT);
    nerf_small_kernel<<<blocks, TPB, SMEM_BYTES>>>(x, ws0, ws1, ws2, wc0, wc1, wc2, wc3, out, n);
}

// round 4
// speedup vs baseline: 3.8557x; 3.6349x over previous
#include <cuda_runtime.h>
#include <cuda_bf16.h>
#include <cstdint>

constexpr int TPB  = 128;   // 4 warps, each owns M=32 rows
constexpr int TILE = 128;

// ---- SMEM layout (bytes) ----
// Weights stored transposed: WT[n][k] bf16, 128B rows (k*2 bytes), XOR-swizzled.
constexpr int WT_ROWS  = 344;                    // 64+64+16+64+64+64+8
constexpr int WT_BYTES = WT_ROWS * 128;          // 44032
constexpr int SM_WHI   = 0;
constexpr int SM_WLO   = WT_BYTES;               // 44032
constexpr int SM_XB    = 2 * WT_BYTES;           // 88064: 4w * 32r * 4 f32 (pts, zero-pad)
constexpr int SM_CIN   = SM_XB + 4*32*4*4;       // 90112: 4w * 32r * 34 f32 (stride 34)
constexpr int SM_OUT   = SM_CIN + 4*32*34*4;     // 107520: 4w * 32r * 4 f32
constexpr int SMEM_TOTAL = SM_OUT + 4*32*4*4;    // 109568 -> 2 CTAs/SM

// region row offsets within a split (rows of 128B)
constexpr int R_S0 = 0,  R_S1 = 64, R_S2 = 128, R_C0 = 144, R_C1 = 208, R_C2 = 272, R_C3 = 336;

// ---------------- PTX helpers ----------------
__device__ __forceinline__ uint32_t smem_u32(const void* p) {
    uint32_t a; asm("{ .reg .u64 t; cvta.to.shared.u64 t, %1; cvt.u32.u64 %0, t; }" : "=r"(a) : "l"(p));
    return a;
}
__device__ __forceinline__ void mma16816(float c[4], const uint32_t a[4], uint32_t b0, uint32_t b1) {
    asm volatile("mma.sync.aligned.m16n8k16.row.col.f32.bf16.bf16.f32 "
        "{%0,%1,%2,%3},{%4,%5,%6,%7},{%8,%9},{%0,%1,%2,%3};"
        : "+f"(c[0]), "+f"(c[1]), "+f"(c[2]), "+f"(c[3])
        : "r"(a[0]), "r"(a[1]), "r"(a[2]), "r"(a[3]), "r"(b0), "r"(b1));
}
__device__ __forceinline__ void ldm4(uint32_t r[4], uint32_t addr) {
    asm volatile("ldmatrix.sync.aligned.m8n8.x4.shared.b16 {%0,%1,%2,%3}, [%4];"
        : "=r"(r[0]), "=r"(r[1]), "=r"(r[2]), "=r"(r[3]) : "r"(addr));
}
__device__ __forceinline__ void ldm2(uint32_t r[2], uint32_t addr) {
    asm volatile("ldmatrix.sync.aligned.m8n8.x2.shared.b16 {%0,%1}, [%2];"
        : "=r"(r[0]), "=r"(r[1]) : "r"(addr));
}
// pack (f0 -> lo, f1 -> hi) as bf16x2 and produce exact lo-residual pack
__device__ __forceinline__ void cvtsplit(float f0, float f1, uint32_t& h, uint32_t& l) {
    uint32_t hh;
    asm("cvt.rn.bf16x2.f32 %0, %1, %2;" : "=r"(hh) : "f"(f1), "f"(f0));
    float r0 = f0 - __uint_as_float(hh << 16);
    float r1 = f1 - __uint_as_float(hh & 0xffff0000u);
    asm("cvt.rn.bf16x2.f32 %0, %1, %2;" : "=r"(l) : "f"(r1), "f"(r0));
    h = hh;
}

// ldmatrix address: B-frag matrices for (n0=16*np .. , k0=16*kt ..)
// x4 matrices: m0=(n0,k0) m1=(n0,k0+8) m2=(n0+8,k0) m3=(n0+8,k0+8)
__device__ __forceinline__ uint32_t ldm_addr4(uint32_t base, int np, int kt, int lane) {
    int m = lane >> 3, r = lane & 7;
    int nrow = np * 16 + ((m >= 2) ? 8 : 0) + r;
    int koff = 32 * kt + ((m & 1) ? 16 : 0);          // bytes within row
    return base + (uint32_t)(nrow * 128 + (koff ^ (r << 4)));
}
__device__ __forceinline__ uint32_t ldm_addr2(uint32_t base, int kt, int lane) {
    int m = (lane >> 3) & 1, r = lane & 7;
    int koff = 32 * kt + (m ? 16 : 0);
    return base + (uint32_t)(r * 128 + (koff ^ (r << 4)));
}

// ---- one layer: C = split3( A x W ), A frags in regs, W in smem ----
template<int KT, int NT>
__device__ __forceinline__ void layer_mma(uint32_t whi, uint32_t wlo,
                                          const uint32_t ah[2][4][4], const uint32_t al[2][4][4],
                                          float C[2][8][4], int lane)
{
    #pragma unroll
    for (int b = 0; b < 2; b++)
        #pragma unroll
        for (int nt = 0; nt < NT; nt++)
            #pragma unroll
            for (int i = 0; i < 4; i++) C[b][nt][i] = 0.0f;

    if constexpr (NT >= 2) {
        #pragma unroll
        for (int np = 0; np < NT / 2; np++) {
            #pragma unroll
            for (int kt = 0; kt < KT; kt++) {
                uint32_t ad = ldm_addr4(0, np, kt, lane);
                uint32_t bh[4], bl[4];
                ldm4(bh, whi + ad);
                ldm4(bl, wlo + ad);
                // pass 1: Ah*Bh ; pass 2: Al*Bh ; pass 3: Ah*Bl  (interleaved chains)
                #pragma unroll
                for (int b = 0; b < 2; b++) {
                    mma16816(C[b][2*np],   ah[b][kt], bh[0], bh[1]);
                    mma16816(C[b][2*np+1], ah[b][kt], bh[2], bh[3]);
                }
                #pragma unroll
                for (int b = 0; b < 2; b++) {
                    mma16816(C[b][2*np],   al[b][kt], bh[0], bh[1]);
                    mma16816(C[b][2*np+1], al[b][kt], bh[2], bh[3]);
                }
                #pragma unroll
                for (int b = 0; b < 2; b++) {
                    mma16816(C[b][2*np],   ah[b][kt], bl[0], bl[1]);
                    mma16816(C[b][2*np+1], ah[b][kt], bl[2], bl[3]);
                }
            }
        }
    } else {
        #pragma unroll
        for (int kt = 0; kt < KT; kt++) {
            uint32_t ad = ldm_addr2(0, kt, lane);
            uint32_t bh[2], bl[2];
            ldm2(bh, whi + ad);
            ldm2(bl, wlo + ad);
            #pragma unroll
            for (int b = 0; b < 2; b++) mma16816(C[b][0], ah[b][kt], bh[0], bh[1]);
            #pragma unroll
            for (int b = 0; b < 2; b++) mma16816(C[b][0], al[b][kt], bh[0], bh[1]);
            #pragma unroll
            for (int b = 0; b < 2; b++) mma16816(C[b][0], ah[b][kt], bl[0], bl[1]);
        }
    }
}

// relu + bf16 hi/lo split: accumulator frags (N=64) -> next-layer A frags (K=64)
__device__ __forceinline__ void epi_relu(const float C[2][8][4],
                                         uint32_t ah[2][4][4], uint32_t al[2][4][4])
{
    #pragma unroll
    for (int b = 0; b < 2; b++)
        #pragma unroll
        for (int kt = 0; kt < 4; kt++) {
            const float* t0 = C[b][2*kt];
            const float* t1 = C[b][2*kt+1];
            cvtsplit(fmaxf(t0[0],0.f), fmaxf(t0[1],0.f), ah[b][kt][0], al[b][kt][0]);
            cvtsplit(fmaxf(t0[2],0.f), fmaxf(t0[3],0.f), ah[b][kt][1], al[b][kt][1]);
            cvtsplit(fmaxf(t1[0],0.f), fmaxf(t1[1],0.f), ah[b][kt][2], al[b][kt][2]);
            cvtsplit(fmaxf(t1[2],0.f), fmaxf(t1[3],0.f), ah[b][kt][3], al[b][kt][3]);
        }
}

// store one weight matrix W[K][N] (row-major) transposed+swizzled into both splits
__device__ __forceinline__ void fill_w(const float* __restrict__ W, int K, int N,
                                       int region_row, char* smem, int tid)
{
    char* whi = smem + SM_WHI + region_row * 128;
    char* wlo = smem + SM_WLO + region_row * 128;
    for (int idx = tid; idx < K * N; idx += TPB) {
        int k = idx / N, nn = idx % N;
        float v = W[idx];
        __nv_bfloat16 hb = __float2bfloat16(v);
        float lf = v - __bfloat162float(hb);
        __nv_bfloat16 lb = __float2bfloat16(lf);
        uint32_t byte = (uint32_t)(nn * 128 + ((2 * k) ^ ((nn & 7) << 4)));
        *reinterpret_cast<uint16_t*>(whi + byte) = *reinterpret_cast<uint16_t*>(&hb);
        *reinterpret_cast<uint16_t*>(wlo + byte) = *reinterpret_cast<uint16_t*>(&lb);
    }
}

__global__ void __launch_bounds__(TPB, 2) nerf_hmma_kernel(
    const float* __restrict__ x,
    const float* __restrict__ ws0, const float* __restrict__ ws1,
    const float* __restrict__ ws2, const float* __restrict__ wc0,
    const float* __restrict__ wc1, const float* __restrict__ wc2,
    const float* __restrict__ wc3,
    float* __restrict__ out, int n)
{
    extern __shared__ char sm[];
    const uint32_t smb = smem_u32(sm);
    const int tid  = threadIdx.x;
    const int wid  = tid >> 5;
    const int lane = tid & 31;
    const int g4   = lane >> 2;   // groupID (row within 16-block)
    const int m4   = lane & 3;    // thread-in-group (col pair)

    // ---- init: zero weight splits, fill transposed+split weights ----
    for (int t = tid; t < (2 * WT_BYTES) / 4; t += TPB)
        reinterpret_cast<uint32_t*>(sm)[t] = 0u;
    __syncthreads();
    fill_w(ws0,  3, 64, R_S0, sm, tid);
    fill_w(ws1, 64, 64, R_S1, sm, tid);
    fill_w(ws2, 64, 16, R_S2, sm, tid);
    fill_w(wc0, 18, 64, R_C0, sm, tid);
    fill_w(wc1, 64, 64, R_C1, sm, tid);
    fill_w(wc2, 64, 64, R_C2, sm, tid);
    fill_w(wc3, 64,  3, R_C3, sm, tid);
    __syncthreads();

    // per-warp staging buffers
    float* xb   = reinterpret_cast<float*>(sm + SM_XB  + wid * 32 * 4 * 4);   // [32][4]
    float* cin  = reinterpret_cast<float*>(sm + SM_CIN + wid * 32 * 34 * 4);  // [32][34]
    float* outb = reinterpret_cast<float*>(sm + SM_OUT + wid * 32 * 4 * 4);   // [32][4]

    // zero cin cols 18..31 once (never overwritten)
    #pragma unroll
    for (int c = 18; c < 32; c++) cin[lane * 34 + c] = 0.0f;
    __syncwarp();

    const uint32_t Whi = smb + SM_WHI, Wlo = smb + SM_WLO;
    const uint32_t wS0h = Whi + R_S0*128, wS0l = Wlo + R_S0*128;
    const uint32_t wS1h = Whi + R_S1*128, wS1l = Wlo + R_S1*128;
    const uint32_t wS2h = Whi + R_S2*128, wS2l = Wlo + R_S2*128;
    const uint32_t wC0h = Whi + R_C0*128, wC0l = Wlo + R_C0*128;
    const uint32_t wC1h = Whi + R_C1*128, wC1l = Wlo + R_C1*128;
    const uint32_t wC2h = Whi + R_C2*128, wC2l = Wlo + R_C2*128;
    const uint32_t wC3h = Whi + R_C3*128, wC3l = Wlo + R_C3*128;

    const int ntiles = n / TILE;

    for (int tile = blockIdx.x; tile < ntiles; tile += gridDim.x) {
        const int rowg = tile * TILE + wid * 32;      // this warp's global row base

        // ---- stage inputs: lane l owns row l ----
        {
            const float* xr = x + (size_t)(rowg + lane) * 6;
            float2 f0 = *reinterpret_cast<const float2*>(xr);
            float2 f1 = *reinterpret_cast<const float2*>(xr + 2);
            float2 f2 = *reinterpret_cast<const float2*>(xr + 4);
            xb[lane*4+0] = f0.x; xb[lane*4+1] = f0.y; xb[lane*4+2] = f1.x; xb[lane*4+3] = 0.0f;
            cin[lane*34+0] = f1.y; cin[lane*34+1] = f2.x; cin[lane*34+2] = f2.y;  // views
        }
        __syncwarp();

        uint32_t ah[2][4][4], al[2][4][4];
        float C[2][8][4];

        // ---- build S0 A frags (K=16: pts in cols 0..2, rest zero) ----
        #pragma unroll
        for (int b = 0; b < 2; b++) {
            int r0 = b*16 + g4, r1 = r0 + 8;
            float v00=0.f, v01=0.f, v10=0.f, v11=0.f;
            if (m4 < 2) {
                v00 = xb[r0*4 + 2*m4]; v01 = xb[r0*4 + 2*m4 + 1];
                v10 = xb[r1*4 + 2*m4]; v11 = xb[r1*4 + 2*m4 + 1];
            }
            cvtsplit(v00, v01, ah[b][0][0], al[b][0][0]);
            cvtsplit(v10, v11, ah[b][0][1], al[b][0][1]);
            ah[b][0][2] = al[b][0][2] = 0u;
            ah[b][0][3] = al[b][0][3] = 0u;
        }

        // ---- S0: 16 -> 64 ---- then S1: 64 -> 64 ----
        layer_mma<1, 8>(wS0h, wS0l, ah, al, C, lane);
        epi_relu(C, ah, al);
        layer_mma<4, 8>(wS1h, wS1l, ah, al, C, lane);
        epi_relu(C, ah, al);

        // ---- S2: 64 -> 16 (no relu) ----
        layer_mma<4, 2>(wS2h, wS2l, ah, al, C, lane);
        // scatter: col0 -> softplus -> outb[.][3]; cols1..15 -> cin[3..17]
        #pragma unroll
        for (int b = 0; b < 2; b++) {
            int r0 = b*16 + g4, r1 = r0 + 8;
            #pragma unroll
            for (int j = 0; j < 2; j++) {
                int c0 = 8*j + 2*m4;
                float v0 = C[b][j][0], v1 = C[b][j][1], v2 = C[b][j][2], v3 = C[b][j][3];
                if (c0 == 0) {
                    outb[r0*4+3] = fmaxf(v0,0.f) + log1pf(expf(-fabsf(v0)));
                    outb[r1*4+3] = fmaxf(v2,0.f) + log1pf(expf(-fabsf(v2)));
                } else {
                    cin[r0*34 + c0+2] = v0;
                    cin[r1*34 + c0+2] = v2;
                }
                cin[r0*34 + c0+3] = v1;
                cin[r1*34 + c0+3] = v3;
            }
        }
        __syncwarp();

        // ---- build C0 A frags from cin (K=32) ----
        #pragma unroll
        for (int b = 0; b < 2; b++) {
            int r0 = b*16 + g4, r1 = r0 + 8;
            #pragma unroll
            for (int kt = 0; kt < 2; kt++) {
                int c = 16*kt + 2*m4;
                float2 p0 = *reinterpret_cast<const float2*>(&cin[r0*34 + c]);
                float2 p1 = *reinterpret_cast<const float2*>(&cin[r1*34 + c]);
                float2 p2 = *reinterpret_cast<const float2*>(&cin[r0*34 + c + 8]);
                float2 p3 = *reinterpret_cast<const float2*>(&cin[r1*34 + c + 8]);
                cvtsplit(p0.x, p0.y, ah[b][kt][0], al[b][kt][0]);
                cvtsplit(p1.x, p1.y, ah[b][kt][1], al[b][kt][1]);
                cvtsplit(p2.x, p2.y, ah[b][kt][2], al[b][kt][2]);
                cvtsplit(p3.x, p3.y, ah[b][kt][3], al[b][kt][3]);
            }
        }

        // ---- C0: 32 -> 64; C1, C2: 64 -> 64 ----
        layer_mma<2, 8>(wC0h, wC0l, ah, al, C, lane);
        epi_relu(C, ah, al);
        layer_mma<4, 8>(wC1h, wC1l, ah, al, C, lane);
        epi_relu(C, ah, al);
        layer_mma<4, 8>(wC2h, wC2l, ah, al, C, lane);
        epi_relu(C, ah, al);

        // ---- C3: 64 -> 3 (N padded to 8) ----
        layer_mma<4, 1>(wC3h, wC3l, ah, al, C, lane);
        #pragma unroll
        for (int b = 0; b < 2; b++) {
            int r0 = b*16 + g4, r1 = r0 + 8;
            if (m4 == 0) {
                outb[r0*4+0] = C[b][0][0]; outb[r0*4+1] = C[b][0][1];
                outb[r1*4+0] = C[b][0][2]; outb[r1*4+1] = C[b][0][3];
            } else if (m4 == 1) {
                outb[r0*4+2] = C[b][0][0];
                outb[r1*4+2] = C[b][0][2];
            }
        }
        __syncwarp();

        // ---- final store: lane l writes row l ----
        {
            float4 r;
            r.x = outb[lane*4+0]; r.y = outb[lane*4+1];
            r.z = outb[lane*4+2]; r.w = outb[lane*4+3];
            reinterpret_cast<float4*>(out)[rowg + lane] = r;
        }
        __syncwarp();
    }
}

extern "C" void kernel_launch(void* const* d_in, const int* in_sizes, int n_in,
                              void* d_out, int out_size) {
    const float* x   = (const float*)d_in[0];
    const float* ws0 = (const float*)d_in[1];
    const float* ws1 = (const float*)d_in[2];
    const float* ws2 = (const float*)d_in[3];
    const float* wc0 = (const float*)d_in[4];
    const float* wc1 = (const float*)d_in[5];
    const float* wc2 = (const float*)d_in[6];
    const float* wc3 = (const float*)d_in[7];
    float* out = (float*)d_out;

    int n = in_sizes[0] / 6;
    int ntiles = n / TILE;

    cudaFuncSetAttribute(nerf_hmma_kernel,
                         cudaFuncAttributeMaxDynamicSharedMemorySize, SMEM_TOTAL);
    int grid = 296;                      // 2 persistent CTAs per SM
    if (grid > ntiles) grid = ntiles;
    nerf_hmma_kernel<<<grid, TPB, SMEM_TOTAL>>>(x, ws0, ws1, ws2, wc0, wc1, wc2, wc3, out, n);
}

// round 5
// speedup vs baseline: 5.4184x; 1.4053x over previous
#include <cuda_runtime.h>
#include <cuda_fp16.h>
#include <cstdint>

constexpr int TPB  = 128;   // 4 warps, each owns M=32 rows
constexpr int TILE = 128;

// ---- SMEM layout (bytes) ----
// Weights stored transposed: WT[n][k] fp16, 128B rows (k*2 bytes), XOR-swizzled.
constexpr int WT_ROWS  = 344;                    // 64+64+16+64+64+64+8
constexpr int WT_BYTES = WT_ROWS * 128;          // 44032
constexpr int SM_W     = 0;
constexpr int SM_XB    = WT_BYTES;               // 44032: 4w * 32r * 4 f32
constexpr int SM_CIN   = SM_XB + 4*32*4*4;       // 46080: 4w * 32r * 34 f32 (stride 34)
constexpr int SM_OUT   = SM_CIN + 4*32*34*4;     // 63488: 4w * 32r * 4 f32
constexpr int SMEM_TOTAL = SM_OUT + 4*32*4*4;    // 65536 -> 3 CTAs/SM

// region row offsets within the weight block (rows of 128B)
constexpr int R_S0 = 0,  R_S1 = 64, R_S2 = 128, R_C0 = 144, R_C1 = 208, R_C2 = 272, R_C3 = 336;

// ---------------- PTX helpers ----------------
__device__ __forceinline__ uint32_t smem_u32(const void* p) {
    uint32_t a; asm("{ .reg .u64 t; cvta.to.shared.u64 t, %1; cvt.u32.u64 %0, t; }" : "=r"(a) : "l"(p));
    return a;
}
__device__ __forceinline__ void mma16816(float c[4], const uint32_t a[4], uint32_t b0, uint32_t b1) {
    asm volatile("mma.sync.aligned.m16n8k16.row.col.f32.f16.f16.f32 "
        "{%0,%1,%2,%3},{%4,%5,%6,%7},{%8,%9},{%0,%1,%2,%3};"
        : "+f"(c[0]), "+f"(c[1]), "+f"(c[2]), "+f"(c[3])
        : "r"(a[0]), "r"(a[1]), "r"(a[2]), "r"(a[3]), "r"(b0), "r"(b1));
}
__device__ __forceinline__ void ldm4(uint32_t r[4], uint32_t addr) {
    asm volatile("ldmatrix.sync.aligned.m8n8.x4.shared.b16 {%0,%1,%2,%3}, [%4];"
        : "=r"(r[0]), "=r"(r[1]), "=r"(r[2]), "=r"(r[3]) : "r"(addr));
}
__device__ __forceinline__ void ldm2(uint32_t r[2], uint32_t addr) {
    asm volatile("ldmatrix.sync.aligned.m8n8.x2.shared.b16 {%0,%1}, [%2];"
        : "=r"(r[0]), "=r"(r[1]) : "r"(addr));
}
// pack (f0 -> lo half, f1 -> hi half) as f16x2; also produce exact fp16 residual pack
__device__ __forceinline__ void cvtsplit(float f0, float f1, uint32_t& h, uint32_t& l) {
    uint32_t hh;
    asm("cvt.rn.f16x2.f32 %0, %1, %2;" : "=r"(hh) : "f"(f1), "f"(f0));
    __half2 h2 = *reinterpret_cast<__half2*>(&hh);
    float2 hf = __half22float2(h2);            // hf.x = f0 rounded, hf.y = f1 rounded
    float r0 = f0 - hf.x;
    float r1 = f1 - hf.y;
    asm("cvt.rn.f16x2.f32 %0, %1, %2;" : "=r"(l) : "f"(r1), "f"(r0));
    h = hh;
}

// ldmatrix address: B-frag matrices for (n0=16*np, k0=16*kt)
__device__ __forceinline__ uint32_t ldm_addr4(uint32_t base, int np, int kt, int lane) {
    int m = lane >> 3, r = lane & 7;
    int nrow = np * 16 + ((m >= 2) ? 8 : 0) + r;
    int koff = 32 * kt + ((m & 1) ? 16 : 0);
    return base + (uint32_t)(nrow * 128 + (koff ^ (r << 4)));
}
__device__ __forceinline__ uint32_t ldm_addr2(uint32_t base, int kt, int lane) {
    int m = (lane >> 3) & 1, r = lane & 7;
    int koff = 32 * kt + (m ? 16 : 0);
    return base + (uint32_t)(r * 128 + (koff ^ (r << 4)));
}

// ---- one layer: C = Ah*W + Al*W (A fp16 hi/lo, W single fp16) ----
template<int KT, int NT>
__device__ __forceinline__ void layer_mma(uint32_t w,
                                          const uint32_t ah[2][4][4], const uint32_t al[2][4][4],
                                          float C[2][8][4], int lane)
{
    #pragma unroll
    for (int b = 0; b < 2; b++)
        #pragma unroll
        for (int nt = 0; nt < NT; nt++)
            #pragma unroll
            for (int i = 0; i < 4; i++) C[b][nt][i] = 0.0f;

    if constexpr (NT >= 2) {
        #pragma unroll
        for (int np = 0; np < NT / 2; np++) {
            #pragma unroll
            for (int kt = 0; kt < KT; kt++) {
                uint32_t bh[4];
                ldm4(bh, w + ldm_addr4(0, np, kt, lane));
                #pragma unroll
                for (int b = 0; b < 2; b++) {
                    mma16816(C[b][2*np],   ah[b][kt], bh[0], bh[1]);
                    mma16816(C[b][2*np+1], ah[b][kt], bh[2], bh[3]);
                }
                #pragma unroll
                for (int b = 0; b < 2; b++) {
                    mma16816(C[b][2*np],   al[b][kt], bh[0], bh[1]);
                    mma16816(C[b][2*np+1], al[b][kt], bh[2], bh[3]);
                }
            }
        }
    } else {
        #pragma unroll
        for (int kt = 0; kt < KT; kt++) {
            uint32_t bh[2];
            ldm2(bh, w + ldm_addr2(0, kt, lane));
            #pragma unroll
            for (int b = 0; b < 2; b++) mma16816(C[b][0], ah[b][kt], bh[0], bh[1]);
            #pragma unroll
            for (int b = 0; b < 2; b++) mma16816(C[b][0], al[b][kt], bh[0], bh[1]);
        }
    }
}

// relu + fp16 hi/lo split: accumulator frags (N=64) -> next-layer A frags (K=64)
__device__ __forceinline__ void epi_relu(const float C[2][8][4],
                                         uint32_t ah[2][4][4], uint32_t al[2][4][4])
{
    #pragma unroll
    for (int b = 0; b < 2; b++)
        #pragma unroll
        for (int kt = 0; kt < 4; kt++) {
            const float* t0 = C[b][2*kt];
            const float* t1 = C[b][2*kt+1];
            cvtsplit(fmaxf(t0[0],0.f), fmaxf(t0[1],0.f), ah[b][kt][0], al[b][kt][0]);
            cvtsplit(fmaxf(t0[2],0.f), fmaxf(t0[3],0.f), ah[b][kt][1], al[b][kt][1]);
            cvtsplit(fmaxf(t1[0],0.f), fmaxf(t1[1],0.f), ah[b][kt][2], al[b][kt][2]);
            cvtsplit(fmaxf(t1[2],0.f), fmaxf(t1[3],0.f), ah[b][kt][3], al[b][kt][3]);
        }
}

// store one weight matrix W[K][N] (row-major) transposed+swizzled, single fp16
__device__ __forceinline__ void fill_w(const float* __restrict__ W, int K, int N,
                                       int region_row, char* smem, int tid)
{
    char* wdst = smem + SM_W + region_row * 128;
    for (int idx = tid; idx < K * N; idx += TPB) {
        int k = idx / N, nn = idx % N;
        __half hb = __float2half(W[idx]);
        uint32_t byte = (uint32_t)(nn * 128 + ((2 * k) ^ ((nn & 7) << 4)));
        *reinterpret_cast<uint16_t*>(wdst + byte) = *reinterpret_cast<uint16_t*>(&hb);
    }
}

__global__ void __launch_bounds__(TPB, 3) nerf_hmma_kernel(
    const float* __restrict__ x,
    const float* __restrict__ ws0, const float* __restrict__ ws1,
    const float* __restrict__ ws2, const float* __restrict__ wc0,
    const float* __restrict__ wc1, const float* __restrict__ wc2,
    const float* __restrict__ wc3,
    float* __restrict__ out, int n)
{
    extern __shared__ char sm[];
    const uint32_t smb = smem_u32(sm);
    const int tid  = threadIdx.x;
    const int wid  = tid >> 5;
    const int lane = tid & 31;
    const int g4   = lane >> 2;
    const int m4   = lane & 3;

    // ---- init: zero weight block (covers K/N padding), fill transposed weights ----
    for (int t = tid; t < WT_BYTES / 4; t += TPB)
        reinterpret_cast<uint32_t*>(sm)[t] = 0u;
    __syncthreads();
    fill_w(ws0,  3, 64, R_S0, sm, tid);
    fill_w(ws1, 64, 64, R_S1, sm, tid);
    fill_w(ws2, 64, 16, R_S2, sm, tid);
    fill_w(wc0, 18, 64, R_C0, sm, tid);
    fill_w(wc1, 64, 64, R_C1, sm, tid);
    fill_w(wc2, 64, 64, R_C2, sm, tid);
    fill_w(wc3, 64,  3, R_C3, sm, tid);
    __syncthreads();

    // per-warp staging buffers
    float* xb   = reinterpret_cast<float*>(sm + SM_XB  + wid * 32 * 4 * 4);   // [32][4]
    float* cin  = reinterpret_cast<float*>(sm + SM_CIN + wid * 32 * 34 * 4);  // [32][34]
    float* outb = reinterpret_cast<float*>(sm + SM_OUT + wid * 32 * 4 * 4);   // [32][4]

    // zero cin cols 18..31 once
    #pragma unroll
    for (int c = 18; c < 32; c++) cin[lane * 34 + c] = 0.0f;
    __syncwarp();

    const uint32_t Wb = smb + SM_W;
    const uint32_t wS0 = Wb + R_S0*128;
    const uint32_t wS1 = Wb + R_S1*128;
    const uint32_t wS2 = Wb + R_S2*128;
    const uint32_t wC0 = Wb + R_C0*128;
    const uint32_t wC1 = Wb + R_C1*128;
    const uint32_t wC2 = Wb + R_C2*128;
    const uint32_t wC3 = Wb + R_C3*128;

    const int ntiles = n / TILE;

    for (int tile = blockIdx.x; tile < ntiles; tile += gridDim.x) {
        const int rowg = tile * TILE + wid * 32;

        // ---- stage inputs: lane l owns row l ----
        {
            const float* xr = x + (size_t)(rowg + lane) * 6;
            float2 f0 = *reinterpret_cast<const float2*>(xr);
            float2 f1 = *reinterpret_cast<const float2*>(xr + 2);
            float2 f2 = *reinterpret_cast<const float2*>(xr + 4);
            xb[lane*4+0] = f0.x; xb[lane*4+1] = f0.y; xb[lane*4+2] = f1.x; xb[lane*4+3] = 0.0f;
            cin[lane*34+0] = f1.y; cin[lane*34+1] = f2.x; cin[lane*34+2] = f2.y;
        }
        __syncwarp();

        uint32_t ah[2][4][4], al[2][4][4];
        float C[2][8][4];

        // ---- build S0 A frags (K=16: pts in cols 0..2, rest zero) ----
        #pragma unroll
        for (int b = 0; b < 2; b++) {
            int r0 = b*16 + g4, r1 = r0 + 8;
            float v00=0.f, v01=0.f, v10=0.f, v11=0.f;
            if (m4 < 2) {
                v00 = xb[r0*4 + 2*m4]; v01 = xb[r0*4 + 2*m4 + 1];
                v10 = xb[r1*4 + 2*m4]; v11 = xb[r1*4 + 2*m4 + 1];
            }
            cvtsplit(v00, v01, ah[b][0][0], al[b][0][0]);
            cvtsplit(v10, v11, ah[b][0][1], al[b][0][1]);
            ah[b][0][2] = al[b][0][2] = 0u;
            ah[b][0][3] = al[b][0][3] = 0u;
        }

        // ---- S0: 16 -> 64; S1: 64 -> 64 ----
        layer_mma<1, 8>(wS0, ah, al, C, lane);
        epi_relu(C, ah, al);
        layer_mma<4, 8>(wS1, ah, al, C, lane);
        epi_relu(C, ah, al);

        // ---- S2: 64 -> 16 (no relu) ----
        layer_mma<4, 2>(wS2, ah, al, C, lane);
        #pragma unroll
        for (int b = 0; b < 2; b++) {
            int r0 = b*16 + g4, r1 = r0 + 8;
            #pragma unroll
            for (int j = 0; j < 2; j++) {
                int c0 = 8*j + 2*m4;
                float v0 = C[b][j][0], v1 = C[b][j][1], v2 = C[b][j][2], v3 = C[b][j][3];
                if (c0 == 0) {
                    outb[r0*4+3] = fmaxf(v0,0.f) + log1pf(expf(-fabsf(v0)));
                    outb[r1*4+3] = fmaxf(v2,0.f) + log1pf(expf(-fabsf(v2)));
                } else {
                    cin[r0*34 + c0+2] = v0;
                    cin[r1*34 + c0+2] = v2;
                }
                cin[r0*34 + c0+3] = v1;
                cin[r1*34 + c0+3] = v3;
            }
        }
        __syncwarp();

        // ---- build C0 A frags from cin (K=32) ----
        #pragma unroll
        for (int b = 0; b < 2; b++) {
            int r0 = b*16 + g4, r1 = r0 + 8;
            #pragma unroll
            for (int kt = 0; kt < 2; kt++) {
                int c = 16*kt + 2*m4;
                float2 p0 = *reinterpret_cast<const float2*>(&cin[r0*34 + c]);
                float2 p1 = *reinterpret_cast<const float2*>(&cin[r1*34 + c]);
                float2 p2 = *reinterpret_cast<const float2*>(&cin[r0*34 + c + 8]);
                float2 p3 = *reinterpret_cast<const float2*>(&cin[r1*34 + c + 8]);
                cvtsplit(p0.x, p0.y, ah[b][kt][0], al[b][kt][0]);
                cvtsplit(p1.x, p1.y, ah[b][kt][1], al[b][kt][1]);
                cvtsplit(p2.x, p2.y, ah[b][kt][2], al[b][kt][2]);
                cvtsplit(p3.x, p3.y, ah[b][kt][3], al[b][kt][3]);
            }
        }

        // ---- C0: 32 -> 64; C1, C2: 64 -> 64 ----
        layer_mma<2, 8>(wC0, ah, al, C, lane);
        epi_relu(C, ah, al);
        layer_mma<4, 8>(wC1, ah, al, C, lane);
        epi_relu(C, ah, al);
        layer_mma<4, 8>(wC2, ah, al, C, lane);
        epi_relu(C, ah, al);

        // ---- C3: 64 -> 3 (N padded to 8) ----
        layer_mma<4, 1>(wC3, ah, al, C, lane);
        #pragma unroll
        for (int b = 0; b < 2; b++) {
            int r0 = b*16 + g4, r1 = r0 + 8;
            if (m4 == 0) {
                outb[r0*4+0] = C[b][0][0]; outb[r0*4+1] = C[b][0][1];
                outb[r1*4+0] = C[b][0][2]; outb[r1*4+1] = C[b][0][3];
            } else if (m4 == 1) {
                outb[r0*4+2] = C[b][0][0];
                outb[r1*4+2] = C[b][0][2];
            }
        }
        __syncwarp();

        // ---- final store ----
        {
            float4 r;
            r.x = outb[lane*4+0]; r.y = outb[lane*4+1];
            r.z = outb[lane*4+2]; r.w = outb[lane*4+3];
            reinterpret_cast<float4*>(out)[rowg + lane] = r;
        }
        __syncwarp();
    }
}

extern "C" void kernel_launch(void* const* d_in, const int* in_sizes, int n_in,
                              void* d_out, int out_size) {
    const float* x   = (const float*)d_in[0];
    const float* ws0 = (const float*)d_in[1];
    const float* ws1 = (const float*)d_in[2];
    const float* ws2 = (const float*)d_in[3];
    const float* wc0 = (const float*)d_in[4];
    const float* wc1 = (const float*)d_in[5];
    const float* wc2 = (const float*)d_in[6];
    const float* wc3 = (const float*)d_in[7];
    float* out = (float*)d_out;

    int n = in_sizes[0] / 6;
    int ntiles = n / TILE;

    cudaFuncSetAttribute(nerf_hmma_kernel,
                         cudaFuncAttributeMaxDynamicSharedMemorySize, SMEM_TOTAL);
    int grid = 444;                      // 3 persistent CTAs per SM
    if (grid > ntiles) grid = ntiles;
    nerf_hmma_kernel<<<grid, TPB, SMEM_TOTAL>>>(x, ws0, ws1, ws2, wc0, wc1, wc2, wc3, out, n);
}

// round 6
// speedup vs baseline: 9.7974x; 1.8082x over previous
#include <cuda_runtime.h>
#include <cuda_fp16.h>
#include <cstdint>

constexpr int TPB  = 128;   // 4 warps, each owns M=32 rows
constexpr int TILE = 128;

// ---- SMEM layout (bytes) ----
// Weights stored transposed: WT[n][k] fp16, 128B rows (k*2 bytes), XOR-swizzled.
constexpr int WT_ROWS  = 344;                    // 64+64+16+64+64+64+8
constexpr int WT_BYTES = WT_ROWS * 128;          // 44032
constexpr int SM_W     = 0;
constexpr int SM_XB    = WT_BYTES;               // 44032: 4w * 32r * 4 f32
constexpr int SM_CIN   = SM_XB + 4*32*4*4;       // 46080: 4w * 32r * 34 f32 (stride 34)
constexpr int SM_OUT   = SM_CIN + 4*32*34*4;     // 63488: 4w * 32r * 4 f32
constexpr int SMEM_TOTAL = SM_OUT + 4*32*4*4;    // 65536 -> 3 CTAs/SM

// region row offsets within the weight block (rows of 128B)
constexpr int R_S0 = 0,  R_S1 = 64, R_S2 = 128, R_C0 = 144, R_C1 = 208, R_C2 = 272, R_C3 = 336;

// ---------------- PTX helpers ----------------
__device__ __forceinline__ uint32_t smem_u32(const void* p) {
    uint32_t a; asm("{ .reg .u64 t; cvta.to.shared.u64 t, %1; cvt.u32.u64 %0, t; }" : "=r"(a) : "l"(p));
    return a;
}
__device__ __forceinline__ void mma16816(float c[4], const uint32_t a[4], uint32_t b0, uint32_t b1) {
    asm volatile("mma.sync.aligned.m16n8k16.row.col.f32.f16.f16.f32 "
        "{%0,%1,%2,%3},{%4,%5,%6,%7},{%8,%9},{%0,%1,%2,%3};"
        : "+f"(c[0]), "+f"(c[1]), "+f"(c[2]), "+f"(c[3])
        : "r"(a[0]), "r"(a[1]), "r"(a[2]), "r"(a[3]), "r"(b0), "r"(b1));
}
__device__ __forceinline__ void ldm4(uint32_t r[4], uint32_t addr) {
    asm volatile("ldmatrix.sync.aligned.m8n8.x4.shared.b16 {%0,%1,%2,%3}, [%4];"
        : "=r"(r[0]), "=r"(r[1]), "=r"(r[2]), "=r"(r[3]) : "r"(addr));
}
__device__ __forceinline__ void ldm2(uint32_t r[2], uint32_t addr) {
    asm volatile("ldmatrix.sync.aligned.m8n8.x2.shared.b16 {%0,%1}, [%2];"
        : "=r"(r[0]), "=r"(r[1]) : "r"(addr));
}
// pack (f0 -> lo half, f1 -> hi half) as f16x2
__device__ __forceinline__ uint32_t pack2(float f0, float f1) {
    uint32_t h;
    asm("cvt.rn.f16x2.f32 %0, %1, %2;" : "=r"(h) : "f"(f1), "f"(f0));
    return h;
}

// ldmatrix address: B-frag matrices for (n0=16*np, k0=16*kt)
__device__ __forceinline__ uint32_t ldm_addr4(uint32_t base, int np, int kt, int lane) {
    int m = lane >> 3, r = lane & 7;
    int nrow = np * 16 + ((m >= 2) ? 8 : 0) + r;
    int koff = 32 * kt + ((m & 1) ? 16 : 0);
    return base + (uint32_t)(nrow * 128 + (koff ^ (r << 4)));
}
__device__ __forceinline__ uint32_t ldm_addr2(uint32_t base, int kt, int lane) {
    int m = (lane >> 3) & 1, r = lane & 7;
    int koff = 32 * kt + (m ? 16 : 0);
    return base + (uint32_t)(r * 128 + (koff ^ (r << 4)));
}

// ---- one layer: C = A x W, single-pass fp16 ----
template<int KT, int NT>
__device__ __forceinline__ void layer_mma(uint32_t w,
                                          const uint32_t ah[2][4][4],
                                          float C[2][8][4], int lane)
{
    #pragma unroll
    for (int b = 0; b < 2; b++)
        #pragma unroll
        for (int nt = 0; nt < NT; nt++)
            #pragma unroll
            for (int i = 0; i < 4; i++) C[b][nt][i] = 0.0f;

    if constexpr (NT >= 2) {
        #pragma unroll
        for (int np = 0; np < NT / 2; np++) {
            #pragma unroll
            for (int kt = 0; kt < KT; kt++) {
                uint32_t bh[4];
                ldm4(bh, w + ldm_addr4(0, np, kt, lane));
                #pragma unroll
                for (int b = 0; b < 2; b++) {
                    mma16816(C[b][2*np],   ah[b][kt], bh[0], bh[1]);
                    mma16816(C[b][2*np+1], ah[b][kt], bh[2], bh[3]);
                }
            }
        }
    } else {
        #pragma unroll
        for (int kt = 0; kt < KT; kt++) {
            uint32_t bh[2];
            ldm2(bh, w + ldm_addr2(0, kt, lane));
            #pragma unroll
            for (int b = 0; b < 2; b++) mma16816(C[b][0], ah[b][kt], bh[0], bh[1]);
        }
    }
}

// relu + fp16 pack: accumulator frags (N=64) -> next-layer A frags (K=64)
__device__ __forceinline__ void epi_relu(const float C[2][8][4], uint32_t ah[2][4][4])
{
    #pragma unroll
    for (int b = 0; b < 2; b++)
        #pragma unroll
        for (int kt = 0; kt < 4; kt++) {
            const float* t0 = C[b][2*kt];
            const float* t1 = C[b][2*kt+1];
            ah[b][kt][0] = pack2(fmaxf(t0[0],0.f), fmaxf(t0[1],0.f));
            ah[b][kt][1] = pack2(fmaxf(t0[2],0.f), fmaxf(t0[3],0.f));
            ah[b][kt][2] = pack2(fmaxf(t1[0],0.f), fmaxf(t1[1],0.f));
            ah[b][kt][3] = pack2(fmaxf(t1[2],0.f), fmaxf(t1[3],0.f));
        }
}

// store one weight matrix W[K][N] (row-major) transposed+swizzled, single fp16
__device__ __forceinline__ void fill_w(const float* __restrict__ W, int K, int N,
                                       int region_row, char* smem, int tid)
{
    char* wdst = smem + SM_W + region_row * 128;
    for (int idx = tid; idx < K * N; idx += TPB) {
        int k = idx / N, nn = idx % N;
        __half hb = __float2half(W[idx]);
        uint32_t byte = (uint32_t)(nn * 128 + ((2 * k) ^ ((nn & 7) << 4)));
        *reinterpret_cast<uint16_t*>(wdst + byte) = *reinterpret_cast<uint16_t*>(&hb);
    }
}

__global__ void __launch_bounds__(TPB, 3) nerf_hmma_kernel(
    const float* __restrict__ x,
    const float* __restrict__ ws0, const float* __restrict__ ws1,
    const float* __restrict__ ws2, const float* __restrict__ wc0,
    const float* __restrict__ wc1, const float* __restrict__ wc2,
    const float* __restrict__ wc3,
    float* __restrict__ out, int n)
{
    extern __shared__ char sm[];
    const uint32_t smb = smem_u32(sm);
    const int tid  = threadIdx.x;
    const int wid  = tid >> 5;
    const int lane = tid & 31;
    const int g4   = lane >> 2;
    const int m4   = lane & 3;

    // ---- init: zero weight block (covers K/N padding), fill transposed weights ----
    for (int t = tid; t < WT_BYTES / 4; t += TPB)
        reinterpret_cast<uint32_t*>(sm)[t] = 0u;
    __syncthreads();
    fill_w(ws0,  3, 64, R_S0, sm, tid);
    fill_w(ws1, 64, 64, R_S1, sm, tid);
    fill_w(ws2, 64, 16, R_S2, sm, tid);
    fill_w(wc0, 18, 64, R_C0, sm, tid);
    fill_w(wc1, 64, 64, R_C1, sm, tid);
    fill_w(wc2, 64, 64, R_C2, sm, tid);
    fill_w(wc3, 64,  3, R_C3, sm, tid);
    __syncthreads();

    // per-warp staging buffers
    float* xb   = reinterpret_cast<float*>(sm + SM_XB  + wid * 32 * 4 * 4);   // [32][4]
    float* cin  = reinterpret_cast<float*>(sm + SM_CIN + wid * 32 * 34 * 4);  // [32][34]
    float* outb = reinterpret_cast<float*>(sm + SM_OUT + wid * 32 * 4 * 4);   // [32][4]

    // zero cin cols 18..31 once
    #pragma unroll
    for (int c = 18; c < 32; c++) cin[lane * 34 + c] = 0.0f;
    __syncwarp();

    const uint32_t Wb = smb + SM_W;
    const uint32_t wS0 = Wb + R_S0*128;
    const uint32_t wS1 = Wb + R_S1*128;
    const uint32_t wS2 = Wb + R_S2*128;
    const uint32_t wC0 = Wb + R_C0*128;
    const uint32_t wC1 = Wb + R_C1*128;
    const uint32_t wC2 = Wb + R_C2*128;
    const uint32_t wC3 = Wb + R_C3*128;

    const int ntiles = n / TILE;

    for (int tile = blockIdx.x; tile < ntiles; tile += gridDim.x) {
        const int rowg = tile * TILE + wid * 32;

        // ---- stage inputs: lane l owns row l ----
        {
            const float* xr = x + (size_t)(rowg + lane) * 6;
            float2 f0 = *reinterpret_cast<const float2*>(xr);
            float2 f1 = *reinterpret_cast<const float2*>(xr + 2);
            float2 f2 = *reinterpret_cast<const float2*>(xr + 4);
            xb[lane*4+0] = f0.x; xb[lane*4+1] = f0.y; xb[lane*4+2] = f1.x; xb[lane*4+3] = 0.0f;
            cin[lane*34+0] = f1.y; cin[lane*34+1] = f2.x; cin[lane*34+2] = f2.y;
        }
        __syncwarp();

        uint32_t ah[2][4][4];
        float C[2][8][4];

        // ---- build S0 A frags (K=16: pts in cols 0..2, rest zero) ----
        #pragma unroll
        for (int b = 0; b < 2; b++) {
            int r0 = b*16 + g4, r1 = r0 + 8;
            float v00=0.f, v01=0.f, v10=0.f, v11=0.f;
            if (m4 < 2) {
                v00 = xb[r0*4 + 2*m4]; v01 = xb[r0*4 + 2*m4 + 1];
                v10 = xb[r1*4 + 2*m4]; v11 = xb[r1*4 + 2*m4 + 1];
            }
            ah[b][0][0] = pack2(v00, v01);
            ah[b][0][1] = pack2(v10, v11);
            ah[b][0][2] = 0u;
            ah[b][0][3] = 0u;
        }

        // ---- S0: 16 -> 64; S1: 64 -> 64 ----
        layer_mma<1, 8>(wS0, ah, C, lane);
        epi_relu(C, ah);
        layer_mma<4, 8>(wS1, ah, C, lane);
        epi_relu(C, ah);

        // ---- S2: 64 -> 16 (no relu) ----
        layer_mma<4, 2>(wS2, ah, C, lane);
        #pragma unroll
        for (int b = 0; b < 2; b++) {
            int r0 = b*16 + g4, r1 = r0 + 8;
            #pragma unroll
            for (int j = 0; j < 2; j++) {
                int c0 = 8*j + 2*m4;
                float v0 = C[b][j][0], v1 = C[b][j][1], v2 = C[b][j][2], v3 = C[b][j][3];
                if (c0 == 0) {
                    outb[r0*4+3] = fmaxf(v0,0.f) + log1pf(expf(-fabsf(v0)));
                    outb[r1*4+3] = fmaxf(v2,0.f) + log1pf(expf(-fabsf(v2)));
                } else {
                    cin[r0*34 + c0+2] = v0;
                    cin[r1*34 + c0+2] = v2;
                }
                cin[r0*34 + c0+3] = v1;
                cin[r1*34 + c0+3] = v3;
            }
        }
        __syncwarp();

        // ---- build C0 A frags from cin (K=32) ----
        #pragma unroll
        for (int b = 0; b < 2; b++) {
            int r0 = b*16 + g4, r1 = r0 + 8;
            #pragma unroll
            for (int kt = 0; kt < 2; kt++) {
                int c = 16*kt + 2*m4;
                float2 p0 = *reinterpret_cast<const float2*>(&cin[r0*34 + c]);
                float2 p1 = *reinterpret_cast<const float2*>(&cin[r1*34 + c]);
                float2 p2 = *reinterpret_cast<const float2*>(&cin[r0*34 + c + 8]);
                float2 p3 = *reinterpret_cast<const float2*>(&cin[r1*34 + c + 8]);
                ah[b][kt][0] = pack2(p0.x, p0.y);
                ah[b][kt][1] = pack2(p1.x, p1.y);
                ah[b][kt][2] = pack2(p2.x, p2.y);
                ah[b][kt][3] = pack2(p3.x, p3.y);
            }
        }

        // ---- C0: 32 -> 64; C1, C2: 64 -> 64 ----
        layer_mma<2, 8>(wC0, ah, C, lane);
        epi_relu(C, ah);
        layer_mma<4, 8>(wC1, ah, C, lane);
        epi_relu(C, ah);
        layer_mma<4, 8>(wC2, ah, C, lane);
        epi_relu(C, ah);

        // ---- C3: 64 -> 3 (N padded to 8) ----
        layer_mma<4, 1>(wC3, ah, C, lane);
        #pragma unroll
        for (int b = 0; b < 2; b++) {
            int r0 = b*16 + g4, r1 = r0 + 8;
            if (m4 == 0) {
                outb[r0*4+0] = C[b][0][0]; outb[r0*4+1] = C[b][0][1];
                outb[r1*4+0] = C[b][0][2]; outb[r1*4+1] = C[b][0][3];
            } else if (m4 == 1) {
                outb[r0*4+2] = C[b][0][0];
                outb[r1*4+2] = C[b][0][2];
            }
        }
        __syncwarp();

        // ---- final store ----
        {
            float4 r;
            r.x = outb[lane*4+0]; r.y = outb[lane*4+1];
            r.z = outb[lane*4+2]; r.w = outb[lane*4+3];
            reinterpret_cast<float4*>(out)[rowg + lane] = r;
        }
        __syncwarp();
    }
}

extern "C" void kernel_launch(void* const* d_in, const int* in_sizes, int n_in,
                              void* d_out, int out_size) {
    const float* x   = (const float*)d_in[0];
    const float* ws0 = (const float*)d_in[1];
    const float* ws1 = (const float*)d_in[2];
    const float* ws2 = (const float*)d_in[3];
    const float* wc0 = (const float*)d_in[4];
    const float* wc1 = (const float*)d_in[5];
    const float* wc2 = (const float*)d_in[6];
    const float* wc3 = (const float*)d_in[7];
    float* out = (float*)d_out;

    int n = in_sizes[0] / 6;
    int ntiles = n / TILE;

    cudaFuncSetAttribute(nerf_hmma_kernel,
                         cudaFuncAttributeMaxDynamicSharedMemorySize, SMEM_TOTAL);
    int grid = 444;                      // 3 persistent CTAs per SM
    if (grid > ntiles) grid = ntiles;
    nerf_hmma_kernel<<<grid, TPB, SMEM_TOTAL>>>(x, ws0, ws1, ws2, wc0, wc1, wc2, wc3, out, n);
}

// round 7
// speedup vs baseline: 10.0487x; 1.0256x over previous
#include <cuda_runtime.h>
#include <cuda_fp16.h>
#include <cstdint>

constexpr int TPB  = 128;   // 4 warps, each owns M=32 rows
constexpr int TILE = 128;

// ---- SMEM layout (bytes) ----
// Weights transposed: WT[n][k] fp16, rows padded to 144B (128B data + 16B pad).
// 144B stride => row r starts 16B further around the 128B bank wrap than row r-1,
// so the 8 rows of an ldmatrix m8n8 tile hit 8 distinct 16B bank groups: conflict-free,
// and addresses are LINEAR in (np, kt) -> SASS LDSM immediate offsets, no per-access ALU.
constexpr int WROWB    = 144;
constexpr int WT_ROWS  = 344;                    // 64+64+16+64+64+64+8
constexpr int WT_BYTES = WT_ROWS * WROWB;        // 49536
constexpr int SM_W     = 0;
constexpr int SM_XB    = WT_BYTES;               // 49536: 4w * 32r * 4 f32
constexpr int SM_CIN   = SM_XB + 4*32*4*4;       // +2048: 4w * 32r * 34 f32 (stride 34)
constexpr int SM_OUT   = SM_CIN + 4*32*34*4;     // +17408: 4w * 32r * 4 f32
constexpr int SMEM_TOTAL = SM_OUT + 4*32*4*4;    // 71040 -> 3 CTAs/SM

// region row offsets within the weight block
constexpr int R_S0 = 0,  R_S1 = 64, R_S2 = 128, R_C0 = 144, R_C1 = 208, R_C2 = 272, R_C3 = 336;

// ---------------- PTX helpers ----------------
__device__ __forceinline__ uint32_t smem_u32(const void* p) {
    uint32_t a; asm("{ .reg .u64 t; cvta.to.shared.u64 t, %1; cvt.u32.u64 %0, t; }" : "=r"(a) : "l"(p));
    return a;
}
__device__ __forceinline__ void mma16816(float c[4], const uint32_t a[4], uint32_t b0, uint32_t b1) {
    asm volatile("mma.sync.aligned.m16n8k16.row.col.f32.f16.f16.f32 "
        "{%0,%1,%2,%3},{%4,%5,%6,%7},{%8,%9},{%0,%1,%2,%3};"
        : "+f"(c[0]), "+f"(c[1]), "+f"(c[2]), "+f"(c[3])
        : "r"(a[0]), "r"(a[1]), "r"(a[2]), "r"(a[3]), "r"(b0), "r"(b1));
}
__device__ __forceinline__ void ldm4(uint32_t r[4], uint32_t addr) {
    asm volatile("ldmatrix.sync.aligned.m8n8.x4.shared.b16 {%0,%1,%2,%3}, [%4];"
        : "=r"(r[0]), "=r"(r[1]), "=r"(r[2]), "=r"(r[3]) : "r"(addr));
}
__device__ __forceinline__ void ldm2(uint32_t r[2], uint32_t addr) {
    asm volatile("ldmatrix.sync.aligned.m8n8.x2.shared.b16 {%0,%1}, [%2];"
        : "=r"(r[0]), "=r"(r[1]) : "r"(addr));
}
// pack (f0 -> lo half, f1 -> hi half) as f16x2
__device__ __forceinline__ uint32_t pack2(float f0, float f1) {
    uint32_t h;
    asm("cvt.rn.f16x2.f32 %0, %1, %2;" : "=r"(h) : "f"(f1), "f"(f0));
    return h;
}
// packed relu: max.f16x2 against zero
__device__ __forceinline__ uint32_t relu2(uint32_t v) {
    uint32_t r;
    asm("max.f16x2 %0, %1, %2;" : "=r"(r) : "r"(v), "r"(0u));
    return r;
}

// ---- one layer (NT tiles of n8): C = A x W, single-pass fp16 ----
// w4 = region base already adjusted by this lane's ldmatrix offset.
template<int KT, int NT>
__device__ __forceinline__ void layer_mma(uint32_t w4,
                                          const uint32_t ah[2][4][4],
                                          float C[2][8][4])
{
    #pragma unroll
    for (int b = 0; b < 2; b++)
        #pragma unroll
        for (int nt = 0; nt < NT; nt++)
            #pragma unroll
            for (int i = 0; i < 4; i++) C[b][nt][i] = 0.0f;

    #pragma unroll
    for (int np = 0; np < NT / 2; np++) {
        #pragma unroll
        for (int kt = 0; kt < KT; kt++) {
            uint32_t bh[4];
            ldm4(bh, w4 + (uint32_t)(np * 16 * WROWB + kt * 32));
            #pragma unroll
            for (int b = 0; b < 2; b++) {
                mma16816(C[b][2*np],   ah[b][kt], bh[0], bh[1]);
                mma16816(C[b][2*np+1], ah[b][kt], bh[2], bh[3]);
            }
        }
    }
}

// N=8 layer (C3): x2 ldmatrix
template<int KT>
__device__ __forceinline__ void layer_mma_n8(uint32_t w2,
                                             const uint32_t ah[2][4][4],
                                             float C[2][8][4])
{
    #pragma unroll
    for (int b = 0; b < 2; b++)
        #pragma unroll
        for (int i = 0; i < 4; i++) C[b][0][i] = 0.0f;
    #pragma unroll
    for (int kt = 0; kt < KT; kt++) {
        uint32_t bh[2];
        ldm2(bh, w2 + (uint32_t)(kt * 32));
        #pragma unroll
        for (int b = 0; b < 2; b++) mma16816(C[b][0], ah[b][kt], bh[0], bh[1]);
    }
}

// cvt + packed relu: accumulator frags (N=64) -> next-layer A frags (K=64)
__device__ __forceinline__ void epi_relu(const float C[2][8][4], uint32_t ah[2][4][4])
{
    #pragma unroll
    for (int b = 0; b < 2; b++)
        #pragma unroll
        for (int kt = 0; kt < 4; kt++) {
            const float* t0 = C[b][2*kt];
            const float* t1 = C[b][2*kt+1];
            ah[b][kt][0] = relu2(pack2(t0[0], t0[1]));
            ah[b][kt][1] = relu2(pack2(t0[2], t0[3]));
            ah[b][kt][2] = relu2(pack2(t1[0], t1[1]));
            ah[b][kt][3] = relu2(pack2(t1[2], t1[3]));
        }
}

// store one weight matrix W[K][N] (row-major) transposed into padded rows, fp16
__device__ __forceinline__ void fill_w(const float* __restrict__ W, int K, int N,
                                       int region_row, char* smem, int tid)
{
    char* wdst = smem + SM_W + region_row * WROWB;
    for (int idx = tid; idx < K * N; idx += TPB) {
        int k = idx / N, nn = idx % N;
        __half hb = __float2half(W[idx]);
        *reinterpret_cast<uint16_t*>(wdst + nn * WROWB + 2 * k) =
            *reinterpret_cast<uint16_t*>(&hb);
    }
}

__global__ void __launch_bounds__(TPB, 3) nerf_hmma_kernel(
    const float* __restrict__ x,
    const float* __restrict__ ws0, const float* __restrict__ ws1,
    const float* __restrict__ ws2, const float* __restrict__ wc0,
    const float* __restrict__ wc1, const float* __restrict__ wc2,
    const float* __restrict__ wc3,
    float* __restrict__ out, int n)
{
    extern __shared__ char sm[];
    const uint32_t smb = smem_u32(sm);
    const int tid  = threadIdx.x;
    const int wid  = tid >> 5;
    const int lane = tid & 31;
    const int g4   = lane >> 2;
    const int m4   = lane & 3;

    // ---- init: zero weight block (covers K/N padding), fill transposed weights ----
    for (int t = tid; t < WT_BYTES / 4; t += TPB)
        reinterpret_cast<uint32_t*>(sm)[t] = 0u;
    __syncthreads();
    fill_w(ws0,  3, 64, R_S0, sm, tid);
    fill_w(ws1, 64, 64, R_S1, sm, tid);
    fill_w(ws2, 64, 16, R_S2, sm, tid);
    fill_w(wc0, 18, 64, R_C0, sm, tid);
    fill_w(wc1, 64, 64, R_C1, sm, tid);
    fill_w(wc2, 64, 64, R_C2, sm, tid);
    fill_w(wc3, 64,  3, R_C3, sm, tid);
    __syncthreads();

    // per-warp staging buffers
    float* xb   = reinterpret_cast<float*>(sm + SM_XB  + wid * 32 * 4 * 4);   // [32][4]
    float* cin  = reinterpret_cast<float*>(sm + SM_CIN + wid * 32 * 34 * 4);  // [32][34]
    float* outb = reinterpret_cast<float*>(sm + SM_OUT + wid * 32 * 4 * 4);   // [32][4]

    // zero cin cols 18..31 once
    #pragma unroll
    for (int c = 18; c < 32; c++) cin[lane * 34 + c] = 0.0f;
    __syncwarp();

    // per-lane ldmatrix offsets (constant for the whole kernel)
    const int mm = lane >> 3, rr = lane & 7;
    const uint32_t off4 = (uint32_t)((((mm >= 2) ? 8 : 0) + rr) * WROWB + ((mm & 1) ? 16 : 0));
    const uint32_t off2 = (uint32_t)(rr * WROWB + ((mm & 1) ? 16 : 0));

    const uint32_t Wb = smb + SM_W;
    const uint32_t wS0 = Wb + R_S0*WROWB + off4;
    const uint32_t wS1 = Wb + R_S1*WROWB + off4;
    const uint32_t wS2 = Wb + R_S2*WROWB + off4;
    const uint32_t wC0 = Wb + R_C0*WROWB + off4;
    const uint32_t wC1 = Wb + R_C1*WROWB + off4;
    const uint32_t wC2 = Wb + R_C2*WROWB + off4;
    const uint32_t wC3 = Wb + R_C3*WROWB + off2;

    const int ntiles = n / TILE;

    for (int tile = blockIdx.x; tile < ntiles; tile += gridDim.x) {
        const int rowg = tile * TILE + wid * 32;

        // ---- stage inputs: lane l owns row l ----
        {
            const float* xr = x + (size_t)(rowg + lane) * 6;
            float2 f0 = *reinterpret_cast<const float2*>(xr);
            float2 f1 = *reinterpret_cast<const float2*>(xr + 2);
            float2 f2 = *reinterpret_cast<const float2*>(xr + 4);
            xb[lane*4+0] = f0.x; xb[lane*4+1] = f0.y; xb[lane*4+2] = f1.x; xb[lane*4+3] = 0.0f;
            cin[lane*34+0] = f1.y; cin[lane*34+1] = f2.x; cin[lane*34+2] = f2.y;
        }
        __syncwarp();

        uint32_t ah[2][4][4];
        float C[2][8][4];

        // ---- build S0 A frags (K=16: pts in cols 0..2, rest zero) ----
        #pragma unroll
        for (int b = 0; b < 2; b++) {
            int r0 = b*16 + g4, r1 = r0 + 8;
            float v00=0.f, v01=0.f, v10=0.f, v11=0.f;
            if (m4 < 2) {
                v00 = xb[r0*4 + 2*m4]; v01 = xb[r0*4 + 2*m4 + 1];
                v10 = xb[r1*4 + 2*m4]; v11 = xb[r1*4 + 2*m4 + 1];
            }
            ah[b][0][0] = pack2(v00, v01);
            ah[b][0][1] = pack2(v10, v11);
            ah[b][0][2] = 0u;
            ah[b][0][3] = 0u;
        }

        // ---- S0: 16 -> 64; S1: 64 -> 64 ----
        layer_mma<1, 8>(wS0, ah, C);
        epi_relu(C, ah);
        layer_mma<4, 8>(wS1, ah, C);
        epi_relu(C, ah);

        // ---- S2: 64 -> 16 (no relu) ----
        layer_mma<4, 2>(wS2, ah, C);
        #pragma unroll
        for (int b = 0; b < 2; b++) {
            int r0 = b*16 + g4, r1 = r0 + 8;
            #pragma unroll
            for (int j = 0; j < 2; j++) {
                int c0 = 8*j + 2*m4;
                float v0 = C[b][j][0], v1 = C[b][j][1], v2 = C[b][j][2], v3 = C[b][j][3];
                if (c0 == 0) {
                    outb[r0*4+3] = fmaxf(v0,0.f) + log1pf(expf(-fabsf(v0)));
                    outb[r1*4+3] = fmaxf(v2,0.f) + log1pf(expf(-fabsf(v2)));
                } else {
                    cin[r0*34 + c0+2] = v0;
                    cin[r1*34 + c0+2] = v2;
                }
                cin[r0*34 + c0+3] = v1;
                cin[r1*34 + c0+3] = v3;
            }
        }
        __syncwarp();

        // ---- build C0 A frags from cin (K=32) ----
        #pragma unroll
        for (int b = 0; b < 2; b++) {
            int r0 = b*16 + g4, r1 = r0 + 8;
            #pragma unroll
            for (int kt = 0; kt < 2; kt++) {
                int c = 16*kt + 2*m4;
                float2 p0 = *reinterpret_cast<const float2*>(&cin[r0*34 + c]);
                float2 p1 = *reinterpret_cast<const float2*>(&cin[r1*34 + c]);
                float2 p2 = *reinterpret_cast<const float2*>(&cin[r0*34 + c + 8]);
                float2 p3 = *reinterpret_cast<const float2*>(&cin[r1*34 + c + 8]);
                ah[b][kt][0] = pack2(p0.x, p0.y);
                ah[b][kt][1] = pack2(p1.x, p1.y);
                ah[b][kt][2] = pack2(p2.x, p2.y);
                ah[b][kt][3] = pack2(p3.x, p3.y);
            }
        }

        // ---- C0: 32 -> 64; C1, C2: 64 -> 64 ----
        layer_mma<2, 8>(wC0, ah, C);
        epi_relu(C, ah);
        layer_mma<4, 8>(wC1, ah, C);
        epi_relu(C, ah);
        layer_mma<4, 8>(wC2, ah, C);
        epi_relu(C, ah);

        // ---- C3: 64 -> 3 (N padded to 8) ----
        layer_mma_n8<4>(wC3, ah, C);
        #pragma unroll
        for (int b = 0; b < 2; b++) {
            int r0 = b*16 + g4, r1 = r0 + 8;
            if (m4 == 0) {
                outb[r0*4+0] = C[b][0][0]; outb[r0*4+1] = C[b][0][1];
                outb[r1*4+0] = C[b][0][2]; outb[r1*4+1] = C[b][0][3];
            } else if (m4 == 1) {
                outb[r0*4+2] = C[b][0][0];
                outb[r1*4+2] = C[b][0][2];
            }
        }
        __syncwarp();

        // ---- final store ----
        {
            float4 r;
            r.x = outb[lane*4+0]; r.y = outb[lane*4+1];
            r.z = outb[lane*4+2]; r.w = outb[lane*4+3];
            reinterpret_cast<float4*>(out)[rowg + lane] = r;
        }
        __syncwarp();
    }
}

extern "C" void kernel_launch(void* const* d_in, const int* in_sizes, int n_in,
                              void* d_out, int out_size) {
    const float* x   = (const float*)d_in[0];
    const float* ws0 = (const float*)d_in[1];
    const float* ws1 = (const float*)d_in[2];
    const float* ws2 = (const float*)d_in[3];
    const float* wc0 = (const float*)d_in[4];
    const float* wc1 = (const float*)d_in[5];
    const float* wc2 = (const float*)d_in[6];
    const float* wc3 = (const float*)d_in[7];
    float* out = (float*)d_out;

    int n = in_sizes[0] / 6;
    int ntiles = n / TILE;

    cudaFuncSetAttribute(nerf_hmma_kernel,
                         cudaFuncAttributeMaxDynamicSharedMemorySize, SMEM_TOTAL);
    int grid = 444;                      // 3 persistent CTAs per SM
    if (grid > ntiles) grid = ntiles;
    nerf_hmma_kernel<<<grid, TPB, SMEM_TOTAL>>>(x, ws0, ws1, ws2, wc0, wc1, wc2, wc3, out, n);
}

// round 8
// speedup vs baseline: 10.6540x; 1.0602x over previous
#include <cuda_runtime.h>
#include <cuda_fp16.h>
#include <cstdint>

constexpr int TPB  = 128;   // 4 warps, each owns M=32 rows
constexpr int TILE = 128;

// ---- weight SMEM: per-region row strides, all ≡16 (mod 32B groups) odd multiples
// of 16 mod 128 -> ldmatrix conflict-free, linear addressing (SASS immediates).
constexpr int ST_S0 = 48;    // K=16 (32B data)
constexpr int ST_C0 = 80;    // K=32 (64B data)
constexpr int ST_64 = 144;   // K=64 (128B data)

constexpr int RB_S0 = 0;                        // 64 rows x 48
constexpr int RB_S1 = RB_S0 + 64*ST_S0;         // 3072,  64 x 144
constexpr int RB_S2 = RB_S1 + 64*ST_64;         // 12288, 16 x 144
constexpr int RB_C0 = RB_S2 + 16*ST_64;         // 14592, 64 x 80
constexpr int RB_C1 = RB_C0 + 64*ST_C0;         // 19712, 64 x 144
constexpr int RB_C2 = RB_C1 + 64*ST_64;         // 28928, 64 x 144
constexpr int RB_C3 = RB_C2 + 64*ST_64;         // 38144, 8 x 144
constexpr int WT_BYTES = RB_C3 + 8*ST_64;       // 39296

// staging (per-warp, packed fp16 words where possible)
constexpr int SM_XB  = WT_BYTES;                // 4w * 32r * 2 u32  = 1024
constexpr int SM_CIN = SM_XB + 4*32*2*4;        // 4w * 32r * 20 u32 = 10240 (stride 20: bank-clean)
constexpr int SM_OUT = SM_CIN + 4*32*20*4;      // 4w * 32r * 5 f32  = 2560 (stride 5: bank-clean)
constexpr int SMEM_TOTAL = SM_OUT + 4*32*5*4;   // 53120 -> 4 CTAs/SM

// ---------------- PTX helpers ----------------
__device__ __forceinline__ uint32_t smem_u32(const void* p) {
    uint32_t a; asm("{ .reg .u64 t; cvta.to.shared.u64 t, %1; cvt.u32.u64 %0, t; }" : "=r"(a) : "l"(p));
    return a;
}
__device__ __forceinline__ void mma16816(float c[4], const uint32_t a[4], uint32_t b0, uint32_t b1) {
    asm volatile("mma.sync.aligned.m16n8k16.row.col.f32.f16.f16.f32 "
        "{%0,%1,%2,%3},{%4,%5,%6,%7},{%8,%9},{%0,%1,%2,%3};"
        : "+f"(c[0]), "+f"(c[1]), "+f"(c[2]), "+f"(c[3])
        : "r"(a[0]), "r"(a[1]), "r"(a[2]), "r"(a[3]), "r"(b0), "r"(b1));
}
__device__ __forceinline__ void ldm4(uint32_t r[4], uint32_t addr) {
    asm volatile("ldmatrix.sync.aligned.m8n8.x4.shared.b16 {%0,%1,%2,%3}, [%4];"
        : "=r"(r[0]), "=r"(r[1]), "=r"(r[2]), "=r"(r[3]) : "r"(addr));
}
__device__ __forceinline__ void ldm2(uint32_t r[2], uint32_t addr) {
    asm volatile("ldmatrix.sync.aligned.m8n8.x2.shared.b16 {%0,%1}, [%2];"
        : "=r"(r[0]), "=r"(r[1]) : "r"(addr));
}
__device__ __forceinline__ uint32_t pack2(float f0, float f1) {
    uint32_t h;
    asm("cvt.rn.f16x2.f32 %0, %1, %2;" : "=r"(h) : "f"(f1), "f"(f0));
    return h;
}
__device__ __forceinline__ uint32_t relu2(uint32_t v) {
    uint32_t r;
    asm("max.f16x2 %0, %1, %2;" : "=r"(r) : "r"(v), "r"(0u));
    return r;
}

// ---- streamed layer: per n-pair, MMA-accumulate over kt, then pack into aout[np] ----
template<int KT, int NP, int STRIDE, int RBASE>
__device__ __forceinline__ void layer_stream(uint32_t abase,
                                             const uint32_t ain[2][4][4],
                                             uint32_t aout[2][4][4])
{
    #pragma unroll
    for (int np = 0; np < NP; np++) {
        float C[2][2][4];
        #pragma unroll
        for (int b = 0; b < 2; b++)
            #pragma unroll
            for (int nt = 0; nt < 2; nt++)
                #pragma unroll
                for (int i = 0; i < 4; i++) C[b][nt][i] = 0.0f;
        #pragma unroll
        for (int kt = 0; kt < KT; kt++) {
            uint32_t bh[4];
            ldm4(bh, abase + (uint32_t)(RBASE + np * 16 * STRIDE + kt * 32));
            #pragma unroll
            for (int b = 0; b < 2; b++) {
                mma16816(C[b][0], ain[b][kt], bh[0], bh[1]);
                mma16816(C[b][1], ain[b][kt], bh[2], bh[3]);
            }
        }
        #pragma unroll
        for (int b = 0; b < 2; b++) {
            aout[b][np][0] = relu2(pack2(C[b][0][0], C[b][0][1]));
            aout[b][np][1] = relu2(pack2(C[b][0][2], C[b][0][3]));
            aout[b][np][2] = relu2(pack2(C[b][1][0], C[b][1][1]));
            aout[b][np][3] = relu2(pack2(C[b][1][2], C[b][1][3]));
        }
    }
}

// store W[K][N] (row-major) transposed into padded rows, fp16
__device__ __forceinline__ void fill_w(const float* __restrict__ W, int K, int N,
                                       int rbase, int stride, char* smem, int tid)
{
    char* wdst = smem + rbase;
    for (int idx = tid; idx < K * N; idx += TPB) {
        int k = idx / N, nn = idx % N;
        __half hb = __float2half(W[idx]);
        *reinterpret_cast<uint16_t*>(wdst + nn * stride + 2 * k) =
            *reinterpret_cast<uint16_t*>(&hb);
    }
}
// wc0 with permuted K rows: src rows 0..2 (views) -> dest k 16..18; src 3..17 (g1..15) -> dest 1..15.
// dest k=0 (g0/sigma column) and 19..31 stay zero.
__device__ __forceinline__ void fill_wc0(const float* __restrict__ W, char* smem, int tid)
{
    char* wdst = smem + RB_C0;
    for (int idx = tid; idx < 18 * 64; idx += TPB) {
        int k = idx / 64, nn = idx % 64;
        int kd = (k < 3) ? (16 + k) : (k - 2);
        __half hb = __float2half(W[idx]);
        *reinterpret_cast<uint16_t*>(wdst + nn * ST_C0 + 2 * kd) =
            *reinterpret_cast<uint16_t*>(&hb);
    }
}

__global__ void __launch_bounds__(TPB, 4) nerf_hmma_kernel(
    const float* __restrict__ x,
    const float* __restrict__ ws0, const float* __restrict__ ws1,
    const float* __restrict__ ws2, const float* __restrict__ wc0,
    const float* __restrict__ wc1, const float* __restrict__ wc2,
    const float* __restrict__ wc3,
    float* __restrict__ out, int n)
{
    extern __shared__ char sm[];
    const uint32_t smb = smem_u32(sm);
    const int tid  = threadIdx.x;
    const int wid  = tid >> 5;
    const int lane = tid & 31;
    const int g4   = lane >> 2;
    const int m4   = lane & 3;

    // ---- init: zero everything (covers K/N padding + constant-zero staging words) ----
    for (int t = tid; t < SMEM_TOTAL / 4; t += TPB)
        reinterpret_cast<uint32_t*>(sm)[t] = 0u;
    __syncthreads();
    fill_w(ws0,  3, 64, RB_S0, ST_S0, sm, tid);
    fill_w(ws1, 64, 64, RB_S1, ST_64, sm, tid);
    fill_w(ws2, 64, 16, RB_S2, ST_64, sm, tid);
    fill_wc0(wc0, sm, tid);
    fill_w(wc1, 64, 64, RB_C1, ST_64, sm, tid);
    fill_w(wc2, 64, 64, RB_C2, ST_64, sm, tid);
    fill_w(wc3, 64,  3, RB_C3, ST_64, sm, tid);
    __syncthreads();

    // per-lane ldmatrix base addresses (one per stride class)
    const int mm = lane >> 3, rr = lane & 7;
    const int qrow = ((mm >= 2) ? 8 : 0) + rr;
    const uint32_t tsel = (mm & 1) ? 16u : 0u;
    const uint32_t a48  = smb + (uint32_t)(qrow * ST_S0) + tsel;
    const uint32_t a80  = smb + (uint32_t)(qrow * ST_C0) + tsel;
    const uint32_t a144 = smb + (uint32_t)(qrow * ST_64) + tsel;
    const uint32_t a2   = smb + (uint32_t)(rr   * ST_64) + tsel;   // ldm2 (C3)

    // per-warp staging (packed fp16 words / padded f32)
    uint32_t* xb  = reinterpret_cast<uint32_t*>(sm + SM_XB)  + wid * 32 * 2;   // [32][2]
    uint32_t* cin = reinterpret_cast<uint32_t*>(sm + SM_CIN) + wid * 32 * 20;  // [32][20]
    float*    outb= reinterpret_cast<float*>(sm + SM_OUT)    + wid * 32 * 5;   // [32][5]

    const int ntiles = n / TILE;

    #pragma unroll 1
    for (int tile = blockIdx.x; tile < ntiles; tile += gridDim.x) {
        const int rowg = tile * TILE + wid * 32;

        // ---- stage inputs: lane l owns row l (packed fp16) ----
        {
            const float* xr = x + (size_t)(rowg + lane) * 6;
            float2 f0 = *reinterpret_cast<const float2*>(xr);
            float2 f1 = *reinterpret_cast<const float2*>(xr + 2);
            float2 f2 = *reinterpret_cast<const float2*>(xr + 4);
            xb[lane*2 + 0]   = pack2(f0.x, f0.y);        // pts x,y
            xb[lane*2 + 1]   = pack2(f1.x, 0.0f);        // pts z, pad
            cin[lane*20 + 8] = pack2(f1.y, f2.x);        // views -> cols 16,17
            cin[lane*20 + 9] = pack2(f2.y, 0.0f);        // view  -> col 18, pad
        }
        __syncwarp();

        uint32_t A0[2][4][4], A1[2][4][4];

        // ---- build S0 A frags (K=16: pts words 0..1, rest zero) ----
        #pragma unroll
        for (int b = 0; b < 2; b++) {
            int r0 = b*16 + g4, r1 = r0 + 8;
            A0[b][0][0] = (m4 < 2) ? xb[r0*2 + m4] : 0u;
            A0[b][0][1] = (m4 < 2) ? xb[r1*2 + m4] : 0u;
            A0[b][0][2] = 0u;
            A0[b][0][3] = 0u;
        }

        // ---- S0: 16 -> 64; S1: 64 -> 64 ----
        layer_stream<1, 4, ST_S0, RB_S0>(a48,  A0, A1);
        layer_stream<4, 4, ST_64, RB_S1>(a144, A1, A0);

        // ---- S2: 64 -> 16 (no relu), scatter packed into cin words 0..7 + sigma ----
        {
            float Cs[2][2][4];
            #pragma unroll
            for (int b = 0; b < 2; b++)
                #pragma unroll
                for (int j = 0; j < 2; j++)
                    #pragma unroll
                    for (int i = 0; i < 4; i++) Cs[b][j][i] = 0.0f;
            #pragma unroll
            for (int kt = 0; kt < 4; kt++) {
                uint32_t bh[4];
                ldm4(bh, a144 + (uint32_t)(RB_S2 + kt * 32));
                #pragma unroll
                for (int b = 0; b < 2; b++) {
                    mma16816(Cs[b][0], A0[b][kt], bh[0], bh[1]);
                    mma16816(Cs[b][1], A0[b][kt], bh[2], bh[3]);
                }
            }
            #pragma unroll
            for (int b = 0; b < 2; b++) {
                int r0 = b*16 + g4, r1 = r0 + 8;
                #pragma unroll
                for (int j = 0; j < 2; j++) {
                    float v0 = Cs[b][j][0], v1 = Cs[b][j][1];
                    float v2 = Cs[b][j][2], v3 = Cs[b][j][3];
                    cin[r0*20 + 4*j + m4] = pack2(v0, v1);   // g cols (c0, c0+1)
                    cin[r1*20 + 4*j + m4] = pack2(v2, v3);
                    if (j == 0 && m4 == 0) {                 // c0==0: sigma = softplus(g0)
                        outb[r0*5 + 3] = fmaxf(v0,0.f) + log1pf(expf(-fabsf(v0)));
                        outb[r1*5 + 3] = fmaxf(v2,0.f) + log1pf(expf(-fabsf(v2)));
                    }
                }
            }
        }
        __syncwarp();

        // ---- build C0 A frags: direct packed-word loads (K=32) ----
        #pragma unroll
        for (int b = 0; b < 2; b++) {
            int r0 = b*16 + g4, r1 = r0 + 8;
            #pragma unroll
            for (int kt = 0; kt < 2; kt++) {
                A0[b][kt][0] = cin[r0*20 + 8*kt + m4];
                A0[b][kt][1] = cin[r1*20 + 8*kt + m4];
                A0[b][kt][2] = cin[r0*20 + 8*kt + m4 + 4];
                A0[b][kt][3] = cin[r1*20 + 8*kt + m4 + 4];
            }
        }

        // ---- C0: 32 -> 64; C1, C2: 64 -> 64 ----
        layer_stream<2, 4, ST_C0, RB_C0>(a80,  A0, A1);
        layer_stream<4, 4, ST_64, RB_C1>(a144, A1, A0);
        layer_stream<4, 4, ST_64, RB_C2>(a144, A0, A1);

        // ---- C3: 64 -> 3 (N padded to 8) ----
        {
            float Cc[2][4];
            #pragma unroll
            for (int b = 0; b < 2; b++)
                #pragma unroll
                for (int i = 0; i < 4; i++) Cc[b][i] = 0.0f;
            #pragma unroll
            for (int kt = 0; kt < 4; kt++) {
                uint32_t bh[2];
                ldm2(bh, a2 + (uint32_t)(RB_C3 + kt * 32));
                #pragma unroll
                for (int b = 0; b < 2; b++) mma16816(Cc[b], A1[b][kt], bh[0], bh[1]);
            }
            #pragma unroll
            for (int b = 0; b < 2; b++) {
                int r0 = b*16 + g4, r1 = r0 + 8;
                if (m4 == 0) {
                    outb[r0*5+0] = Cc[b][0]; outb[r0*5+1] = Cc[b][1];
                    outb[r1*5+0] = Cc[b][2]; outb[r1*5+1] = Cc[b][3];
                } else if (m4 == 1) {
                    outb[r0*5+2] = Cc[b][0];
                    outb[r1*5+2] = Cc[b][2];
                }
            }
        }
        __syncwarp();

        // ---- final store: lane l writes row l ----
        {
            float4 r;
            r.x = outb[lane*5+0]; r.y = outb[lane*5+1];
            r.z = outb[lane*5+2]; r.w = outb[lane*5+3];
            reinterpret_cast<float4*>(out)[rowg + lane] = r;
        }
        __syncwarp();
    }
}

extern "C" void kernel_launch(void* const* d_in, const int* in_sizes, int n_in,
                              void* d_out, int out_size) {
    const float* x   = (const float*)d_in[0];
    const float* ws0 = (const float*)d_in[1];
    const float* ws1 = (const float*)d_in[2];
    const float* ws2 = (const float*)d_in[3];
    const float* wc0 = (const float*)d_in[4];
    const float* wc1 = (const float*)d_in[5];
    const float* wc2 = (const float*)d_in[6];
    const float* wc3 = (const float*)d_in[7];
    float* out = (float*)d_out;

    int n = in_sizes[0] / 6;
    int ntiles = n / TILE;

    cudaFuncSetAttribute(nerf_hmma_kernel,
                         cudaFuncAttributeMaxDynamicSharedMemorySize, SMEM_TOTAL);
    int grid = 592;                      // 4 persistent CTAs per SM
    if (grid > ntiles) grid = ntiles;
    nerf_hmma_kernel<<<grid, TPB, SMEM_TOTAL>>>(x, ws0, ws1, ws2, wc0, wc1, wc2, wc3, out, n);
}

// round 9
// speedup vs baseline: 10.6872x; 1.0031x over previous
#include <cuda_runtime.h>
#include <cuda_fp16.h>
#include <cstdint>

constexpr int TPB  = 128;   // 4 warps, each owns M=32 rows
constexpr int TILE = 128;

// ---- weight SMEM: per-region row strides ≡ 16·odd (mod 128) -> ldmatrix
// conflict-free, linear addressing (SASS immediate offsets).
constexpr int ST_S0 = 48;    // K=16 (32B data)
constexpr int ST_C0 = 80;    // K=32 (64B data)
constexpr int ST_64 = 144;   // K=64 (128B data)

constexpr int RB_S0 = 0;                        // 64 rows x 48
constexpr int RB_S1 = RB_S0 + 64*ST_S0;         // 64 x 144
constexpr int RB_S2 = RB_S1 + 64*ST_64;         // 16 x 144
constexpr int RB_C0 = RB_S2 + 16*ST_64;         // 64 x 80
constexpr int RB_C1 = RB_C0 + 64*ST_C0;         // 64 x 144
constexpr int RB_C2 = RB_C1 + 64*ST_64;         // 64 x 144
constexpr int RB_C3 = RB_C2 + 64*ST_64;         // 8 x 144
constexpr int WT_BYTES = RB_C3 + 8*ST_64;       // 39296

constexpr int SM_OUT = WT_BYTES;                // 4w * 32r * 5 f32 (stride 5: bank-clean)
constexpr int SMEM_TOTAL = SM_OUT + 4*32*5*4;   // 41856 -> 4 CTAs/SM (RF-capped at 4 anyway)

// ---------------- PTX helpers ----------------
__device__ __forceinline__ uint32_t smem_u32(const void* p) {
    uint32_t a; asm("{ .reg .u64 t; cvta.to.shared.u64 t, %1; cvt.u32.u64 %0, t; }" : "=r"(a) : "l"(p));
    return a;
}
__device__ __forceinline__ void mma16816(float c[4], const uint32_t a[4], uint32_t b0, uint32_t b1) {
    asm volatile("mma.sync.aligned.m16n8k16.row.col.f32.f16.f16.f32 "
        "{%0,%1,%2,%3},{%4,%5,%6,%7},{%8,%9},{%0,%1,%2,%3};"
        : "+f"(c[0]), "+f"(c[1]), "+f"(c[2]), "+f"(c[3])
        : "r"(a[0]), "r"(a[1]), "r"(a[2]), "r"(a[3]), "r"(b0), "r"(b1));
}
__device__ __forceinline__ void ldm4(uint32_t r[4], uint32_t addr) {
    asm volatile("ldmatrix.sync.aligned.m8n8.x4.shared.b16 {%0,%1,%2,%3}, [%4];"
        : "=r"(r[0]), "=r"(r[1]), "=r"(r[2]), "=r"(r[3]) : "r"(addr));
}
__device__ __forceinline__ void ldm2(uint32_t r[2], uint32_t addr) {
    asm volatile("ldmatrix.sync.aligned.m8n8.x2.shared.b16 {%0,%1}, [%2];"
        : "=r"(r[0]), "=r"(r[1]) : "r"(addr));
}
__device__ __forceinline__ uint32_t pack2(float f0, float f1) {
    uint32_t h;
    asm("cvt.rn.f16x2.f32 %0, %1, %2;" : "=r"(h) : "f"(f1), "f"(f0));
    return h;
}
__device__ __forceinline__ uint32_t relu2(uint32_t v) {
    uint32_t r;
    asm("max.f16x2 %0, %1, %2;" : "=r"(r) : "r"(v), "r"(0u));
    return r;
}
__device__ __forceinline__ uint32_t shfl_u(uint32_t v, int src) {
    return __shfl_sync(0xffffffffu, v, src);
}

// ---- streamed layer: per n-pair, MMA-accumulate over kt, then pack into aout[np] ----
template<int KT, int NP, int STRIDE, int RBASE>
__device__ __forceinline__ void layer_stream(uint32_t abase,
                                             const uint32_t ain[2][4][4],
                                             uint32_t aout[2][4][4])
{
    #pragma unroll
    for (int np = 0; np < NP; np++) {
        float C[2][2][4];
        #pragma unroll
        for (int b = 0; b < 2; b++)
            #pragma unroll
            for (int nt = 0; nt < 2; nt++)
                #pragma unroll
                for (int i = 0; i < 4; i++) C[b][nt][i] = 0.0f;
        #pragma unroll
        for (int kt = 0; kt < KT; kt++) {
            uint32_t bh[4];
            ldm4(bh, abase + (uint32_t)(RBASE + np * 16 * STRIDE + kt * 32));
            #pragma unroll
            for (int b = 0; b < 2; b++) {
                mma16816(C[b][0], ain[b][kt], bh[0], bh[1]);
                mma16816(C[b][1], ain[b][kt], bh[2], bh[3]);
            }
        }
        #pragma unroll
        for (int b = 0; b < 2; b++) {
            aout[b][np][0] = relu2(pack2(C[b][0][0], C[b][0][1]));
            aout[b][np][1] = relu2(pack2(C[b][0][2], C[b][0][3]));
            aout[b][np][2] = relu2(pack2(C[b][1][0], C[b][1][1]));
            aout[b][np][3] = relu2(pack2(C[b][1][2], C[b][1][3]));
        }
    }
}

// store W[K][N] (row-major) transposed into padded rows, fp16
__device__ __forceinline__ void fill_w(const float* __restrict__ W, int K, int N,
                                       int rbase, int stride, char* smem, int tid)
{
    char* wdst = smem + rbase;
    for (int idx = tid; idx < K * N; idx += TPB) {
        int k = idx / N, nn = idx % N;
        __half hb = __float2half(W[idx]);
        *reinterpret_cast<uint16_t*>(wdst + nn * stride + 2 * k) =
            *reinterpret_cast<uint16_t*>(&hb);
    }
}
// wc0 with permuted K rows: src 0..2 (views) -> k 16..18; src 3..17 (g1..g15) -> k 1..15.
// dest k=0 (sigma/g0 column) and 19..31 stay zero.
__device__ __forceinline__ void fill_wc0(const float* __restrict__ W, char* smem, int tid)
{
    char* wdst = smem + RB_C0;
    for (int idx = tid; idx < 18 * 64; idx += TPB) {
        int k = idx / 64, nn = idx % 64;
        int kd = (k < 3) ? (16 + k) : (k - 2);
        __half hb = __float2half(W[idx]);
        *reinterpret_cast<uint16_t*>(wdst + nn * ST_C0 + 2 * kd) =
            *reinterpret_cast<uint16_t*>(&hb);
    }
}

__global__ void __launch_bounds__(TPB, 4) nerf_hmma_kernel(
    const float* __restrict__ x,
    const float* __restrict__ ws0, const float* __restrict__ ws1,
    const float* __restrict__ ws2, const float* __restrict__ wc0,
    const float* __restrict__ wc1, const float* __restrict__ wc2,
    const float* __restrict__ wc3,
    float* __restrict__ out, int n)
{
    extern __shared__ char sm[];
    const uint32_t smb = smem_u32(sm);
    const int tid  = threadIdx.x;
    const int wid  = tid >> 5;
    const int lane = tid & 31;
    const int g4   = lane >> 2;
    const int m4   = lane & 3;

    // ---- init: zero weights (covers K/N padding), fill transposed weights ----
    for (int t = tid; t < WT_BYTES / 4; t += TPB)
        reinterpret_cast<uint32_t*>(sm)[t] = 0u;
    __syncthreads();
    fill_w(ws0,  3, 64, RB_S0, ST_S0, sm, tid);
    fill_w(ws1, 64, 64, RB_S1, ST_64, sm, tid);
    fill_w(ws2, 64, 16, RB_S2, ST_64, sm, tid);
    fill_wc0(wc0, sm, tid);
    fill_w(wc1, 64, 64, RB_C1, ST_64, sm, tid);
    fill_w(wc2, 64, 64, RB_C2, ST_64, sm, tid);
    fill_w(wc3, 64,  3, RB_C3, ST_64, sm, tid);
    __syncthreads();

    // per-lane ldmatrix base addresses (one per stride class)
    const int mm = lane >> 3, rr = lane & 7;
    const int qrow = ((mm >= 2) ? 8 : 0) + rr;
    const uint32_t tsel = (mm & 1) ? 16u : 0u;
    const uint32_t a48  = smb + (uint32_t)(qrow * ST_S0) + tsel;
    const uint32_t a80  = smb + (uint32_t)(qrow * ST_C0) + tsel;
    const uint32_t a144 = smb + (uint32_t)(qrow * ST_64) + tsel;
    const uint32_t a2   = smb + (uint32_t)(rr   * ST_64) + tsel;   // ldm2 (C3)

    // per-warp output staging (cross-lane assembly for float4 store)
    float* outb = reinterpret_cast<float*>(sm + SM_OUT) + wid * 32 * 5;   // [32][5]

    const int ntiles = n / TILE;

    // ---- prefetch first tile's x into registers ----
    float2 p01, p23, p45;
    int tile = blockIdx.x;
    if (tile < ntiles) {
        const float* xr = x + (size_t)(tile * TILE + wid * 32 + lane) * 6;
        p01 = *reinterpret_cast<const float2*>(xr);
        p23 = *reinterpret_cast<const float2*>(xr + 2);
        p45 = *reinterpret_cast<const float2*>(xr + 4);
    }

    #pragma unroll 1
    for (; tile < ntiles; tile += gridDim.x) {
        const int rowg = tile * TILE + wid * 32;

        // pack this lane's row into fp16 words (lane l owns row l)
        const uint32_t w0 = pack2(p01.x, p01.y);   // pts x,y  (K words 0)
        const uint32_t w1 = pack2(p23.x, 0.0f);    // pts z    (K word 1)
        const uint32_t w8 = pack2(p23.y, p45.x);   // views vx,vy (C0 K word 8)
        const uint32_t w9 = pack2(p45.y, 0.0f);    // view  vz    (C0 K word 9)

        // ---- issue next tile's x load now; latency hides under this tile's MMAs ----
        const int tnext = tile + gridDim.x;
        if (tnext < ntiles) {
            const float* xr = x + (size_t)(tnext * TILE + wid * 32 + lane) * 6;
            p01 = *reinterpret_cast<const float2*>(xr);
            p23 = *reinterpret_cast<const float2*>(xr + 2);
            p45 = *reinterpret_cast<const float2*>(xr + 4);
        }

        uint32_t A0[2][4][4], A1[2][4][4];

        // ---- build S0 A frags via shfl (K=16: pts words 0..1, rest zero) ----
        #pragma unroll
        for (int b = 0; b < 2; b++) {
            int r0 = b*16 + g4, r1 = r0 + 8;
            uint32_t u00 = shfl_u(w0, r0), u01 = shfl_u(w1, r0);
            uint32_t u10 = shfl_u(w0, r1), u11 = shfl_u(w1, r1);
            A0[b][0][0] = (m4 == 0) ? u00 : (m4 == 1) ? u01 : 0u;
            A0[b][0][1] = (m4 == 0) ? u10 : (m4 == 1) ? u11 : 0u;
            A0[b][0][2] = 0u;
            A0[b][0][3] = 0u;
        }

        // ---- S0: 16 -> 64; S1: 64 -> 64 ----
        layer_stream<1, 4, ST_S0, RB_S0>(a48,  A0, A1);
        layer_stream<4, 4, ST_64, RB_S1>(a144, A1, A0);

        // ---- S2: 64 -> 16 (no relu) ----
        float Cs[2][2][4];
        #pragma unroll
        for (int b = 0; b < 2; b++)
            #pragma unroll
            for (int j = 0; j < 2; j++)
                #pragma unroll
                for (int i = 0; i < 4; i++) Cs[b][j][i] = 0.0f;
        #pragma unroll
        for (int kt = 0; kt < 4; kt++) {
            uint32_t bh[4];
            ldm4(bh, a144 + (uint32_t)(RB_S2 + kt * 32));
            #pragma unroll
            for (int b = 0; b < 2; b++) {
                mma16816(Cs[b][0], A0[b][kt], bh[0], bh[1]);
                mma16816(Cs[b][1], A0[b][kt], bh[2], bh[3]);
            }
        }

        // sigma: lane m4==0 holds col 0 (g0) for rows r0 (c0) and r1 (c2)
        #pragma unroll
        for (int b = 0; b < 2; b++) {
            if (m4 == 0) {
                int r0 = b*16 + g4, r1 = r0 + 8;
                float v0 = Cs[b][0][0], v2 = Cs[b][0][2];
                outb[r0*5 + 3] = fmaxf(v0, 0.f) + log1pf(expf(-fabsf(v0)));
                outb[r1*5 + 3] = fmaxf(v2, 0.f) + log1pf(expf(-fabsf(v2)));
            }
        }

        // ---- build C0 A frags: kt=0 = IN-LANE repack of S2 C-frags (word 4j+m4
        //      == exactly what this lane needs); kt=1 = views via shfl ----
        #pragma unroll
        for (int b = 0; b < 2; b++) {
            A0[b][0][0] = pack2(Cs[b][0][0], Cs[b][0][1]);   // row r0, word m4
            A0[b][0][1] = pack2(Cs[b][0][2], Cs[b][0][3]);   // row r1, word m4
            A0[b][0][2] = pack2(Cs[b][1][0], Cs[b][1][1]);   // row r0, word 4+m4
            A0[b][0][3] = pack2(Cs[b][1][2], Cs[b][1][3]);   // row r1, word 4+m4
            int r0 = b*16 + g4, r1 = r0 + 8;
            uint32_t v00 = shfl_u(w8, r0), v01 = shfl_u(w9, r0);
            uint32_t v10 = shfl_u(w8, r1), v11 = shfl_u(w9, r1);
            A0[b][1][0] = (m4 == 0) ? v00 : (m4 == 1) ? v01 : 0u;
            A0[b][1][1] = (m4 == 0) ? v10 : (m4 == 1) ? v11 : 0u;
            A0[b][1][2] = 0u;
            A0[b][1][3] = 0u;
        }

        // ---- C0: 32 -> 64; C1, C2: 64 -> 64 ----
        layer_stream<2, 4, ST_C0, RB_C0>(a80,  A0, A1);
        layer_stream<4, 4, ST_64, RB_C1>(a144, A1, A0);
        layer_stream<4, 4, ST_64, RB_C2>(a144, A0, A1);

        // ---- C3: 64 -> 3 (N padded to 8) ----
        {
            float Cc[2][4];
            #pragma unroll
            for (int b = 0; b < 2; b++)
                #pragma unroll
                for (int i = 0; i < 4; i++) Cc[b][i] = 0.0f;
            #pragma unroll
            for (int kt = 0; kt < 4; kt++) {
                uint32_t bh[2];
                ldm2(bh, a2 + (uint32_t)(RB_C3 + kt * 32));
                #pragma unroll
                for (int b = 0; b < 2; b++) mma16816(Cc[b], A1[b][kt], bh[0], bh[1]);
            }
            #pragma unroll
            for (int b = 0; b < 2; b++) {
                int r0 = b*16 + g4, r1 = r0 + 8;
                if (m4 == 0) {
                    outb[r0*5+0] = Cc[b][0]; outb[r0*5+1] = Cc[b][1];
                    outb[r1*5+0] = Cc[b][2]; outb[r1*5+1] = Cc[b][3];
                } else if (m4 == 1) {
                    outb[r0*5+2] = Cc[b][0];
                    outb[r1*5+2] = Cc[b][2];
                }
            }
        }
        __syncwarp();

        // ---- final store: lane l writes row l ----
        {
            float4 r;
            r.x = outb[lane*5+0]; r.y = outb[lane*5+1];
            r.z = outb[lane*5+2]; r.w = outb[lane*5+3];
            reinterpret_cast<float4*>(out)[rowg + lane] = r;
        }
        __syncwarp();
    }
}

extern "C" void kernel_launch(void* const* d_in, const int* in_sizes, int n_in,
                              void* d_out, int out_size) {
    const float* x   = (const float*)d_in[0];
    const float* ws0 = (const float*)d_in[1];
    const float* ws1 = (const float*)d_in[2];
    const float* ws2 = (const float*)d_in[3];
    const float* wc0 = (const float*)d_in[4];
    const float* wc1 = (const float*)d_in[5];
    const float* wc2 = (const float*)d_in[6];
    const float* wc3 = (const float*)d_in[7];
    float* out = (float*)d_out;

    int n = in_sizes[0] / 6;
    int ntiles = n / TILE;

    cudaFuncSetAttribute(nerf_hmma_kernel,
                         cudaFuncAttributeMaxDynamicSharedMemorySize, SMEM_TOTAL);
    int grid = 592;                      // 4 persistent CTAs per SM
    if (grid > ntiles) grid = ntiles;
    nerf_hmma_kernel<<<grid, TPB, SMEM_TOTAL>>>(x, ws0, ws1, ws2, wc0, wc1, wc2, wc3, out, n);
}